// round 2
// baseline (speedup 1.0000x reference)
#include <cuda_runtime.h>
#include <math.h>

// Problem constants
// B=4, T=2048, D=512, H=8, HD=64, F=2048, WINDOW=128
// rows = B*T = 8192

// ---------------- scratch (device globals; no allocation allowed) ----------------
__device__ float g_x2 [8192 * 512];   // LN1 output
__device__ float g_qkv[8192 * 1536];  // qkv projection
__device__ float g_ctx[8192 * 512];   // attention context
__device__ float g_x3 [8192 * 512];   // LN2 output
__device__ float g_h  [8192 * 2048];  // MLP hidden

// ---------------- LayerNorm: one block (128 threads) per row of 512 ----------------
__global__ void ln_kernel(const float* __restrict__ x, const float* __restrict__ gw,
                          const float* __restrict__ bw, float* __restrict__ out) {
    int row = blockIdx.x;
    int t = threadIdx.x;  // 0..127
    const float* xr = x + (size_t)row * 512;
    float4 v = *(const float4*)(xr + t * 4);
    float s  = v.x + v.y + v.z + v.w;
    float sq = v.x * v.x + v.y * v.y + v.z * v.z + v.w * v.w;
    #pragma unroll
    for (int o = 16; o > 0; o >>= 1) {
        s  += __shfl_xor_sync(0xffffffffu, s,  o);
        sq += __shfl_xor_sync(0xffffffffu, sq, o);
    }
    __shared__ float red[8];
    int wid = t >> 5, lane = t & 31;
    if (lane == 0) { red[wid] = s; red[4 + wid] = sq; }
    __syncthreads();
    float S  = red[0] + red[1] + red[2] + red[3];
    float SQ = red[4] + red[5] + red[6] + red[7];
    float mu   = S * (1.0f / 512.0f);
    float var  = SQ * (1.0f / 512.0f) - mu * mu;
    float rstd = rsqrtf(var + 1e-5f);
    float4 gv = *(const float4*)(gw + t * 4);
    float4 bv = *(const float4*)(bw + t * 4);
    float4 o;
    o.x = (v.x - mu) * rstd * gv.x + bv.x;
    o.y = (v.y - mu) * rstd * gv.y + bv.y;
    o.z = (v.z - mu) * rstd * gv.z + bv.z;
    o.w = (v.w - mu) * rstd * gv.w + bv.w;
    *(float4*)(out + (size_t)row * 512 + t * 4) = o;
}

// ---------------- Tiled fp32 GEMM:  C[M,N] = A[M,K] @ W[N,K]^T + bias (+res)(gelu) ----------------
// BM=BN=128, BK=16, 256 threads, 8x8 microtile per thread (split 4+4 at stride 64).
#define EPI_BIAS      0
#define EPI_BIAS_RES  1
#define EPI_BIAS_GELU 2

template<int EPI>
__global__ __launch_bounds__(256, 2)
void gemm_nt(const float* __restrict__ A, const float* __restrict__ W,
             const float* __restrict__ bias, const float* __restrict__ res,
             float* __restrict__ C, int M, int N, int K) {
    __shared__ __align__(16) float As[16][128];
    __shared__ __align__(16) float Ws[16][128];

    int tid = threadIdx.x;
    int tx = tid & 15;       // 0..15  -> N microtile
    int ty = tid >> 4;       // 0..15  -> M microtile
    int m0 = blockIdx.y * 128;
    int n0 = blockIdx.x * 128;

    int lr = tid >> 2;        // 0..63 (tile row for loads)
    int lc = (tid & 3) << 2;  // 0,4,8,12 (k-col for loads)

    const float* Ap = A + (size_t)(m0 + lr) * K + lc;
    const float* Wp = W + (size_t)(n0 + lr) * K + lc;

    float acc[8][8];
    #pragma unroll
    for (int i = 0; i < 8; i++)
        #pragma unroll
        for (int j = 0; j < 8; j++) acc[i][j] = 0.0f;

    for (int k0 = 0; k0 < K; k0 += 16) {
        float4 a0 = *(const float4*)(Ap);
        float4 a1 = *(const float4*)(Ap + (size_t)64 * K);
        float4 w0 = *(const float4*)(Wp);
        float4 w1 = *(const float4*)(Wp + (size_t)64 * K);
        // store transposed (k-major) into smem
        As[lc + 0][lr] = a0.x; As[lc + 1][lr] = a0.y; As[lc + 2][lr] = a0.z; As[lc + 3][lr] = a0.w;
        As[lc + 0][lr + 64] = a1.x; As[lc + 1][lr + 64] = a1.y; As[lc + 2][lr + 64] = a1.z; As[lc + 3][lr + 64] = a1.w;
        Ws[lc + 0][lr] = w0.x; Ws[lc + 1][lr] = w0.y; Ws[lc + 2][lr] = w0.z; Ws[lc + 3][lr] = w0.w;
        Ws[lc + 0][lr + 64] = w1.x; Ws[lc + 1][lr + 64] = w1.y; Ws[lc + 2][lr + 64] = w1.z; Ws[lc + 3][lr + 64] = w1.w;
        __syncthreads();
        #pragma unroll
        for (int kk = 0; kk < 16; kk++) {
            float ar[8], wr[8];
            *(float4*)&ar[0] = *(const float4*)&As[kk][ty * 4];
            *(float4*)&ar[4] = *(const float4*)&As[kk][64 + ty * 4];
            *(float4*)&wr[0] = *(const float4*)&Ws[kk][tx * 4];
            *(float4*)&wr[4] = *(const float4*)&Ws[kk][64 + tx * 4];
            #pragma unroll
            for (int i = 0; i < 8; i++)
                #pragma unroll
                for (int j = 0; j < 8; j++)
                    acc[i][j] += ar[i] * wr[j];
        }
        __syncthreads();
        Ap += 16;
        Wp += 16;
    }

    // epilogue
    #pragma unroll
    for (int i = 0; i < 8; i++) {
        int row = m0 + (i >> 2) * 64 + ty * 4 + (i & 3);
        #pragma unroll
        for (int jb = 0; jb < 2; jb++) {
            int col = n0 + jb * 64 + tx * 4;
            float4 bv = *(const float4*)(bias + col);
            float o0 = acc[i][jb * 4 + 0] + bv.x;
            float o1 = acc[i][jb * 4 + 1] + bv.y;
            float o2 = acc[i][jb * 4 + 2] + bv.z;
            float o3 = acc[i][jb * 4 + 3] + bv.w;
            if (EPI == EPI_BIAS_GELU) {
                o0 = 0.5f * o0 * (1.0f + erff(o0 * 0.70710678118654752f));
                o1 = 0.5f * o1 * (1.0f + erff(o1 * 0.70710678118654752f));
                o2 = 0.5f * o2 * (1.0f + erff(o2 * 0.70710678118654752f));
                o3 = 0.5f * o3 * (1.0f + erff(o3 * 0.70710678118654752f));
            }
            if (EPI == EPI_BIAS_RES) {
                float4 rv = *(const float4*)(res + (size_t)row * N + col);
                o0 += rv.x; o1 += rv.y; o2 += rv.z; o3 += rv.w;
            }
            float4 o = make_float4(o0, o1, o2, o3);
            *(float4*)(C + (size_t)row * N + col) = o;
        }
    }
}

// ---------------- Sliding-window attention ----------------
// Block: 256 threads handles one (b,h) x 64 queries. Keys span [t0-128, t0+63] in 6 chunks of 32.
// thread -> (q = tid/4, g = tid%4). Scores: thread computes keys g*8..g*8+7.
// Output dims per thread: d = kq*16 + g*4 + r (kq<4, r<4)  -> conflict-free Vs reads.
__global__ __launch_bounds__(256)
void attn_kernel(const float* __restrict__ qkv, float* __restrict__ ctx) {
    __shared__ float Qs[64][65];
    __shared__ float Ks[32][65];
    __shared__ __align__(16) float Vs[32][64];
    __shared__ float Ps[64][33];

    int bh = blockIdx.y;
    int b = bh >> 3, h = bh & 7;
    int t0 = blockIdx.x * 64;
    int tid = threadIdx.x;
    int q = tid >> 2, g = tid & 3;
    const float scale = 0.125f;  // 1/sqrt(64)

    // load Q tile (scaled): 64 rows x 64 cols = 1024 float4s
    for (int i = tid; i < 64 * 16; i += 256) {
        int r = i >> 4, c4 = (i & 15) << 2;
        float4 v = *(const float4*)(qkv + (size_t)(b * 2048 + t0 + r) * 1536 + h * 64 + c4);
        Qs[r][c4 + 0] = v.x * scale;
        Qs[r][c4 + 1] = v.y * scale;
        Qs[r][c4 + 2] = v.z * scale;
        Qs[r][c4 + 3] = v.w * scale;
    }

    float acc[16];
    #pragma unroll
    for (int i = 0; i < 16; i++) acc[i] = 0.0f;
    float row_max = -1e30f, row_sum = 0.0f;
    int t = t0 + q;

    for (int c = 0; c < 6; c++) {
        int kbase = t0 - 128 + c * 32;
        if (kbase + 31 < 0) continue;   // uniform across block
        __syncthreads();                // protect Ks/Vs reuse (also orders Qs stores before reads)
        // load K (scalar, padded stride 65) and V (float4, stride 64)
        for (int i = tid; i < 32 * 16; i += 256) {
            int r = i >> 4, c4 = (i & 15) << 2;
            int s = kbase + r;
            float4 kv = make_float4(0.f, 0.f, 0.f, 0.f);
            float4 vv = make_float4(0.f, 0.f, 0.f, 0.f);
            if (s >= 0) {
                size_t base = (size_t)(b * 2048 + s) * 1536 + h * 64 + c4;
                kv = *(const float4*)(qkv + base + 512);
                vv = *(const float4*)(qkv + base + 1024);
            }
            Ks[r][c4 + 0] = kv.x; Ks[r][c4 + 1] = kv.y; Ks[r][c4 + 2] = kv.z; Ks[r][c4 + 3] = kv.w;
            *(float4*)&Vs[r][c4] = vv;
        }
        __syncthreads();

        // scores for this thread's 8 keys
        float sc[8];
        #pragma unroll
        for (int j = 0; j < 8; j++) sc[j] = 0.0f;
        #pragma unroll 16
        for (int d = 0; d < 64; d++) {
            float qv = Qs[q][d];
            #pragma unroll
            for (int j = 0; j < 8; j++) sc[j] += qv * Ks[g * 8 + j][d];
        }
        // mask: allowed iff 0 <= s <= t and s >= t-127
        float cmax = -1e30f;
        bool al[8];
        #pragma unroll
        for (int j = 0; j < 8; j++) {
            int s = kbase + g * 8 + j;
            al[j] = (s >= 0) && (s <= t) && (s >= t - 127);
            if (!al[j]) sc[j] = -1e30f;
            cmax = fmaxf(cmax, sc[j]);
        }
        cmax = fmaxf(cmax, __shfl_xor_sync(0xffffffffu, cmax, 1));
        cmax = fmaxf(cmax, __shfl_xor_sync(0xffffffffu, cmax, 2));
        float nm = fmaxf(row_max, cmax);
        float corr = __expf(row_max - nm);  // both -1e30 -> exp(0)=1 (acc is 0 anyway)
        float p[8];
        float csum = 0.0f;
        #pragma unroll
        for (int j = 0; j < 8; j++) {
            p[j] = al[j] ? __expf(sc[j] - nm) : 0.0f;
            csum += p[j];
        }
        csum += __shfl_xor_sync(0xffffffffu, csum, 1);
        csum += __shfl_xor_sync(0xffffffffu, csum, 2);
        row_sum = row_sum * corr + csum;
        #pragma unroll
        for (int i = 0; i < 16; i++) acc[i] *= corr;
        row_max = nm;
        #pragma unroll
        for (int j = 0; j < 8; j++) Ps[q][g * 8 + j] = p[j];
        __syncthreads();

        // accumulate: acc[kq*4+r] += P[q][s] * Vs[s][kq*16 + g*4 + r]
        #pragma unroll 4
        for (int s = 0; s < 32; s++) {
            float pv = Ps[q][s];
            #pragma unroll
            for (int kq = 0; kq < 4; kq++) {
                float4 vv = *(const float4*)&Vs[s][kq * 16 + g * 4];
                acc[kq * 4 + 0] += pv * vv.x;
                acc[kq * 4 + 1] += pv * vv.y;
                acc[kq * 4 + 2] += pv * vv.z;
                acc[kq * 4 + 3] += pv * vv.w;
            }
        }
    }

    float inv = 1.0f / row_sum;
    size_t base = (size_t)(b * 2048 + t) * 512 + h * 64;
    #pragma unroll
    for (int kq = 0; kq < 4; kq++) {
        float4 o = make_float4(acc[kq * 4 + 0] * inv, acc[kq * 4 + 1] * inv,
                               acc[kq * 4 + 2] * inv, acc[kq * 4 + 3] * inv);
        *(float4*)(ctx + base + kq * 16 + g * 4) = o;
    }
}

// ---------------- launch ----------------
extern "C" void kernel_launch(void* const* d_in, const int* in_sizes, int n_in,
                              void* d_out, int out_size) {
    const float* x     = (const float*)d_in[0];
    const float* in_w  = (const float*)d_in[1];
    const float* in_b  = (const float*)d_in[2];
    const float* out_w = (const float*)d_in[3];
    const float* out_b = (const float*)d_in[4];
    const float* ln1_g = (const float*)d_in[5];
    const float* ln1_b = (const float*)d_in[6];
    const float* ln2_g = (const float*)d_in[7];
    const float* ln2_b = (const float*)d_in[8];
    const float* w1    = (const float*)d_in[9];
    const float* b1    = (const float*)d_in[10];
    const float* w2    = (const float*)d_in[11];
    const float* b2    = (const float*)d_in[12];
    float* out = (float*)d_out;

    float *px2, *pqkv, *pctx, *px3, *ph;
    cudaGetSymbolAddress((void**)&px2,  g_x2);
    cudaGetSymbolAddress((void**)&pqkv, g_qkv);
    cudaGetSymbolAddress((void**)&pctx, g_ctx);
    cudaGetSymbolAddress((void**)&px3,  g_x3);
    cudaGetSymbolAddress((void**)&ph,   g_h);

    // 1) x2 = LN1(x)
    ln_kernel<<<8192, 128>>>(x, ln1_g, ln1_b, px2);

    // 2) qkv = x2 @ in_w^T + in_b     [8192,1536]
    {
        dim3 grid(1536 / 128, 8192 / 128);
        gemm_nt<EPI_BIAS><<<grid, 256>>>(px2, in_w, in_b, nullptr, pqkv, 8192, 1536, 512);
    }

    // 3) ctx = sliding-window attention(qkv)
    {
        dim3 grid(2048 / 64, 4 * 8);  // (query tiles, B*H)
        attn_kernel<<<grid, 256>>>(pqkv, pctx);
    }

    // 4) out = x + ctx @ out_w^T + out_b   [8192,512]
    {
        dim3 grid(512 / 128, 8192 / 128);
        gemm_nt<EPI_BIAS_RES><<<grid, 256>>>(pctx, out_w, out_b, x, out, 8192, 512, 512);
    }

    // 5) x3 = LN2(out)
    ln_kernel<<<8192, 128>>>(out, ln2_g, ln2_b, px3);

    // 6) h = gelu(x3 @ w1^T + b1)   [8192,2048]
    {
        dim3 grid(2048 / 128, 8192 / 128);
        gemm_nt<EPI_BIAS_GELU><<<grid, 256>>>(px3, w1, b1, nullptr, ph, 8192, 2048, 512);
    }

    // 7) out = out + h @ w2^T + b2   [8192,512]
    {
        dim3 grid(512 / 128, 8192 / 128);
        gemm_nt<EPI_BIAS_RES><<<grid, 256>>>(ph, w2, b2, out, out, 8192, 512, 2048);
    }
}

// round 4
// speedup vs baseline: 1.7981x; 1.7981x over previous
#include <cuda_runtime.h>
#include <cuda_bf16.h>
#include <math.h>
#include <stdint.h>

typedef __nv_bfloat16 bf16;

// B=4, T=2048, D=512, H=8, HD=64, F=2048, WINDOW=128, rows=8192

// ---------------- scratch ----------------
__device__ float g_qkv [8192 * 1536];
__device__ bf16  g_x2h [8192 * 512],  g_x2l [8192 * 512];
__device__ bf16  g_ctxh[8192 * 512],  g_ctxl[8192 * 512];
__device__ bf16  g_x3h [8192 * 512],  g_x3l [8192 * 512];
__device__ bf16  g_hh  [8192 * 2048], g_hl  [8192 * 2048];
__device__ bf16  g_wah [1536 * 512],  g_wal [1536 * 512];
__device__ bf16  g_wbh [512 * 512],   g_wbl [512 * 512];
__device__ bf16  g_w1h [2048 * 512],  g_w1l [2048 * 512];
__device__ bf16  g_w2h [512 * 2048],  g_w2l [512 * 2048];

// ---------------- helpers ----------------
__device__ __forceinline__ uint32_t smem_u32(const void* p) {
    uint32_t a;
    asm("{ .reg .u64 t; cvta.to.shared.u64 t, %1; cvt.u32.u64 %0, t; }" : "=r"(a) : "l"(p));
    return a;
}
__device__ __forceinline__ void cp16(uint32_t d, const void* g) {
    asm volatile("cp.async.cg.shared.global [%0], [%1], 16;" :: "r"(d), "l"(g));
}
#define CP_COMMIT() asm volatile("cp.async.commit_group;" ::: "memory")
#define CP_WAIT(n)  asm volatile("cp.async.wait_group %0;" :: "n"(n) : "memory")

#define LDSM4(r, addr) \
    asm volatile("ldmatrix.sync.aligned.m8n8.x4.shared.b16 {%0,%1,%2,%3}, [%4];" \
        : "=r"((r)[0]), "=r"((r)[1]), "=r"((r)[2]), "=r"((r)[3]) : "r"(addr))

#define MMA16816(c, a, b) \
    asm volatile("mma.sync.aligned.m16n8k16.row.col.f32.bf16.bf16.f32 " \
        "{%0,%1,%2,%3}, {%4,%5,%6,%7}, {%8,%9}, {%0,%1,%2,%3};" \
        : "+f"((c)[0]), "+f"((c)[1]), "+f"((c)[2]), "+f"((c)[3]) \
        : "r"((a)[0]), "r"((a)[1]), "r"((a)[2]), "r"((a)[3]), "r"((b)[0]), "r"((b)[1]))

// ---------------- weight split: fp32 -> (hi, lo) bf16 ----------------
__global__ void split_kernel(const float* __restrict__ w, bf16* __restrict__ hi,
                             bf16* __restrict__ lo, int n4) {
    int i = blockIdx.x * 256 + threadIdx.x;
    if (i >= n4) return;
    float4 v = *(const float4*)(w + i * 4);
    bf16 h0 = __float2bfloat16_rn(v.x), h1 = __float2bfloat16_rn(v.y);
    bf16 h2 = __float2bfloat16_rn(v.z), h3 = __float2bfloat16_rn(v.w);
    bf16 l0 = __float2bfloat16_rn(v.x - __bfloat162float(h0));
    bf16 l1 = __float2bfloat16_rn(v.y - __bfloat162float(h1));
    bf16 l2 = __float2bfloat16_rn(v.z - __bfloat162float(h2));
    bf16 l3 = __float2bfloat16_rn(v.w - __bfloat162float(h3));
    __nv_bfloat162 ha = {h0, h1}, hb = {h2, h3}, la = {l0, l1}, lb = {l2, l3};
    *(__nv_bfloat162*)(hi + i * 4)     = ha;
    *(__nv_bfloat162*)(hi + i * 4 + 2) = hb;
    *(__nv_bfloat162*)(lo + i * 4)     = la;
    *(__nv_bfloat162*)(lo + i * 4 + 2) = lb;
}

// ---------------- LayerNorm with split output ----------------
__global__ void ln_split_kernel(const float* __restrict__ x, const float* __restrict__ gw,
                                const float* __restrict__ bw, bf16* __restrict__ hi,
                                bf16* __restrict__ lo) {
    int row = blockIdx.x;
    int t = threadIdx.x;
    const float* xr = x + (size_t)row * 512;
    float4 v = *(const float4*)(xr + t * 4);
    float s  = v.x + v.y + v.z + v.w;
    float sq = v.x * v.x + v.y * v.y + v.z * v.z + v.w * v.w;
    #pragma unroll
    for (int o = 16; o > 0; o >>= 1) {
        s  += __shfl_xor_sync(0xffffffffu, s,  o);
        sq += __shfl_xor_sync(0xffffffffu, sq, o);
    }
    __shared__ float red[8];
    int wid = t >> 5, lane = t & 31;
    if (lane == 0) { red[wid] = s; red[4 + wid] = sq; }
    __syncthreads();
    float S  = red[0] + red[1] + red[2] + red[3];
    float SQ = red[4] + red[5] + red[6] + red[7];
    float mu   = S * (1.0f / 512.0f);
    float var  = SQ * (1.0f / 512.0f) - mu * mu;
    float rstd = rsqrtf(var + 1e-5f);
    float4 gv = *(const float4*)(gw + t * 4);
    float4 bv = *(const float4*)(bw + t * 4);
    float o0 = (v.x - mu) * rstd * gv.x + bv.x;
    float o1 = (v.y - mu) * rstd * gv.y + bv.y;
    float o2 = (v.z - mu) * rstd * gv.z + bv.z;
    float o3 = (v.w - mu) * rstd * gv.w + bv.w;
    bf16 h0 = __float2bfloat16_rn(o0), h1 = __float2bfloat16_rn(o1);
    bf16 h2 = __float2bfloat16_rn(o2), h3 = __float2bfloat16_rn(o3);
    bf16 l0 = __float2bfloat16_rn(o0 - __bfloat162float(h0));
    bf16 l1 = __float2bfloat16_rn(o1 - __bfloat162float(h1));
    bf16 l2 = __float2bfloat16_rn(o2 - __bfloat162float(h2));
    bf16 l3 = __float2bfloat16_rn(o3 - __bfloat162float(h3));
    size_t base = (size_t)row * 512 + t * 4;
    __nv_bfloat162 ha = {h0, h1}, hb = {h2, h3}, la = {l0, l1}, lb = {l2, l3};
    *(__nv_bfloat162*)(hi + base)     = ha;
    *(__nv_bfloat162*)(hi + base + 2) = hb;
    *(__nv_bfloat162*)(lo + base)     = la;
    *(__nv_bfloat162*)(lo + base + 2) = lb;
}

// ---------------- mma.sync GEMM: C[M,N] = A[M,K] @ W[N,K]^T (3-term bf16 split) ----------------
// CTA tile 128x128, BK=32 bf16, 3-stage cp.async pipeline, 8 warps of 64x32.
// smem tile rows padded: 32+8 bf16 = 80 B stride (ldmatrix conflict-free).
#define EPI_BIAS       0
#define EPI_BIAS_RES   1
#define EPI_GELU_SPLIT 2

#define TPAD     80          // bytes per smem row
#define TILE_B   (128 * TPAD)   // 10240
#define STAGE_B  (4 * TILE_B)   // 40960
#define NSTAGE   3
#define GEMM_SMEM (NSTAGE * STAGE_B)

template<int EPI>
__global__ __launch_bounds__(256)
void gemm_mma(const bf16* __restrict__ Ah, const bf16* __restrict__ Al,
              const bf16* __restrict__ Bh, const bf16* __restrict__ Bl,
              const float* __restrict__ bias, const float* __restrict__ res,
              float* __restrict__ Cf, bf16* __restrict__ Ch, bf16* __restrict__ Cl,
              int N, int K) {
    extern __shared__ char sm[];
    const int tid = threadIdx.x;
    const int lane = tid & 31, wid = tid >> 5;
    const int wm = wid & 1, wn = wid >> 1;           // warp 64x32 tile: (wm, wn)
    const int m0 = blockIdx.y * 128, n0 = blockIdx.x * 128;
    const uint32_t sbase = smem_u32(sm);

    const bf16* srcs[4] = { Ah + (size_t)m0 * K, Al + (size_t)m0 * K,
                            Bh + (size_t)n0 * K, Bl + (size_t)n0 * K };

    // loader: one stage = 4 tiles of 128 rows x 32 bf16
    auto load_stage = [&](int s, int kb) {
        uint32_t so = sbase + (uint32_t)s * STAGE_B;
        #pragma unroll
        for (int tt = 0; tt < 4; tt++) {
            const bf16* gp = srcs[tt] + kb * 32;
            uint32_t tb = so + tt * TILE_B;
            #pragma unroll
            for (int it = 0; it < 2; it++) {
                int idx = tid + it * 256;          // 0..511
                int r = idx >> 2, c = idx & 3;
                cp16(tb + r * TPAD + c * 16, gp + (size_t)r * K + c * 8);
            }
        }
    };

    float acc[4][4][4];
    #pragma unroll
    for (int i = 0; i < 4; i++)
        #pragma unroll
        for (int j = 0; j < 4; j++)
            #pragma unroll
            for (int r = 0; r < 4; r++) acc[i][j][r] = 0.0f;

    const int nkb = K >> 5;

    // prologue: stages 0..NSTAGE-2
    #pragma unroll
    for (int p = 0; p < NSTAGE - 1; p++) {
        if (p < nkb) load_stage(p, p);
        CP_COMMIT();
    }

    // precomputed intra-warp ldmatrix offsets
    const uint32_t aRow = wm * 64 + (lane & 15);          // + i*16
    const uint32_t aChunkHalf = (lane >> 4);              // 0/1 -> +16B within k16
    const uint32_t bRow = wn * 32 + (lane & 7) + ((lane >> 4) << 3);  // + jp*16
    const uint32_t bChunkHalf = (lane >> 3) & 1;

    for (int kb = 0; kb < nkb; kb++) {
        bool more = (kb + NSTAGE - 1) < nkb;
        if (more) load_stage((kb + NSTAGE - 1) % NSTAGE, kb + NSTAGE - 1);
        CP_COMMIT();
        if (more) { CP_WAIT(NSTAGE - 1); } else { CP_WAIT(0); }
        __syncthreads();

        uint32_t so = sbase + (uint32_t)(kb % NSTAGE) * STAGE_B;
        #pragma unroll
        for (int ks = 0; ks < 2; ks++) {
            uint32_t Ahf[4][4], Alf[4][4];
            #pragma unroll
            for (int i = 0; i < 4; i++) {
                uint32_t off = (aRow + i * 16) * TPAD + (ks * 2 + aChunkHalf) * 16;
                LDSM4(Ahf[i], so + off);
                LDSM4(Alf[i], so + TILE_B + off);
            }
            uint32_t Bhf[2][4], Blf[2][4];
            #pragma unroll
            for (int jp = 0; jp < 2; jp++) {
                uint32_t off = (bRow + jp * 16) * TPAD + (ks * 2 + bChunkHalf) * 16;
                LDSM4(Bhf[jp], so + 2 * TILE_B + off);
                LDSM4(Blf[jp], so + 3 * TILE_B + off);
            }
            #pragma unroll
            for (int i = 0; i < 4; i++) {
                #pragma unroll
                for (int j = 0; j < 4; j++) {
                    int jp = j >> 1, jo = (j & 1) * 2;
                    MMA16816(acc[i][j], Ahf[i], (Bhf[jp] + jo));
                    MMA16816(acc[i][j], Ahf[i], (Blf[jp] + jo));
                    MMA16816(acc[i][j], Alf[i], (Bhf[jp] + jo));
                }
            }
        }
        __syncthreads();
    }

    // ---------------- epilogue ----------------
    #pragma unroll
    for (int i = 0; i < 4; i++) {
        int rb = m0 + wm * 64 + i * 16 + (lane >> 2);
        #pragma unroll
        for (int j = 0; j < 4; j++) {
            int col = n0 + wn * 32 + j * 8 + (lane & 3) * 2;
            float b0 = bias[col], b1 = bias[col + 1];
            #pragma unroll
            for (int half = 0; half < 2; half++) {
                int row = rb + half * 8;
                float o0 = acc[i][j][half * 2 + 0] + b0;
                float o1 = acc[i][j][half * 2 + 1] + b1;
                size_t ob = (size_t)row * N + col;
                if (EPI == EPI_BIAS_RES) {
                    float2 rv = *(const float2*)(res + ob);
                    o0 += rv.x; o1 += rv.y;
                }
                if (EPI == EPI_GELU_SPLIT) {
                    o0 = 0.5f * o0 * (1.0f + erff(o0 * 0.70710678118654752f));
                    o1 = 0.5f * o1 * (1.0f + erff(o1 * 0.70710678118654752f));
                    bf16 h0 = __float2bfloat16_rn(o0), h1 = __float2bfloat16_rn(o1);
                    bf16 l0 = __float2bfloat16_rn(o0 - __bfloat162float(h0));
                    bf16 l1 = __float2bfloat16_rn(o1 - __bfloat162float(h1));
                    __nv_bfloat162 hv = {h0, h1}, lv = {l0, l1};
                    *(__nv_bfloat162*)(Ch + ob) = hv;
                    *(__nv_bfloat162*)(Cl + ob) = lv;
                } else {
                    float2 o = make_float2(o0, o1);
                    *(float2*)(Cf + ob) = o;
                }
            }
        }
    }
}

// ---------------- Sliding-window attention (fp32 SIMT, split output) ----------------
__global__ __launch_bounds__(256)
void attn_kernel(const float* __restrict__ qkv, bf16* __restrict__ ctxh, bf16* __restrict__ ctxl) {
    __shared__ float Qs[64][65];
    __shared__ float Ks[32][65];
    __shared__ __align__(16) float Vs[32][64];
    __shared__ float Ps[64][33];

    int bh = blockIdx.y;
    int b = bh >> 3, h = bh & 7;
    int t0 = blockIdx.x * 64;
    int tid = threadIdx.x;
    int q = tid >> 2, g = tid & 3;
    const float scale = 0.125f;

    for (int i = tid; i < 64 * 16; i += 256) {
        int r = i >> 4, c4 = (i & 15) << 2;
        float4 v = *(const float4*)(qkv + (size_t)(b * 2048 + t0 + r) * 1536 + h * 64 + c4);
        Qs[r][c4 + 0] = v.x * scale;
        Qs[r][c4 + 1] = v.y * scale;
        Qs[r][c4 + 2] = v.z * scale;
        Qs[r][c4 + 3] = v.w * scale;
    }

    float acc[16];
    #pragma unroll
    for (int i = 0; i < 16; i++) acc[i] = 0.0f;
    float row_max = -1e30f, row_sum = 0.0f;
    int t = t0 + q;

    for (int c = 0; c < 6; c++) {
        int kbase = t0 - 128 + c * 32;
        if (kbase + 31 < 0) continue;
        __syncthreads();
        for (int i = tid; i < 32 * 16; i += 256) {
            int r = i >> 4, c4 = (i & 15) << 2;
            int s = kbase + r;
            float4 kv = make_float4(0.f, 0.f, 0.f, 0.f);
            float4 vv = make_float4(0.f, 0.f, 0.f, 0.f);
            if (s >= 0) {
                size_t base = (size_t)(b * 2048 + s) * 1536 + h * 64 + c4;
                kv = *(const float4*)(qkv + base + 512);
                vv = *(const float4*)(qkv + base + 1024);
            }
            Ks[r][c4 + 0] = kv.x; Ks[r][c4 + 1] = kv.y; Ks[r][c4 + 2] = kv.z; Ks[r][c4 + 3] = kv.w;
            *(float4*)&Vs[r][c4] = vv;
        }
        __syncthreads();

        float sc[8];
        #pragma unroll
        for (int j = 0; j < 8; j++) sc[j] = 0.0f;
        #pragma unroll 16
        for (int d = 0; d < 64; d++) {
            float qv = Qs[q][d];
            #pragma unroll
            for (int j = 0; j < 8; j++) sc[j] += qv * Ks[g * 8 + j][d];
        }
        float cmax = -1e30f;
        bool al[8];
        #pragma unroll
        for (int j = 0; j < 8; j++) {
            int s = kbase + g * 8 + j;
            al[j] = (s >= 0) && (s <= t) && (s >= t - 127);
            if (!al[j]) sc[j] = -1e30f;
            cmax = fmaxf(cmax, sc[j]);
        }
        cmax = fmaxf(cmax, __shfl_xor_sync(0xffffffffu, cmax, 1));
        cmax = fmaxf(cmax, __shfl_xor_sync(0xffffffffu, cmax, 2));
        float nm = fmaxf(row_max, cmax);
        float corr = __expf(row_max - nm);
        float p[8];
        float csum = 0.0f;
        #pragma unroll
        for (int j = 0; j < 8; j++) {
            p[j] = al[j] ? __expf(sc[j] - nm) : 0.0f;
            csum += p[j];
        }
        csum += __shfl_xor_sync(0xffffffffu, csum, 1);
        csum += __shfl_xor_sync(0xffffffffu, csum, 2);
        row_sum = row_sum * corr + csum;
        #pragma unroll
        for (int i = 0; i < 16; i++) acc[i] *= corr;
        row_max = nm;
        #pragma unroll
        for (int j = 0; j < 8; j++) Ps[q][g * 8 + j] = p[j];
        __syncthreads();

        #pragma unroll 4
        for (int s = 0; s < 32; s++) {
            float pv = Ps[q][s];
            #pragma unroll
            for (int kq = 0; kq < 4; kq++) {
                float4 vv = *(const float4*)&Vs[s][kq * 16 + g * 4];
                acc[kq * 4 + 0] += pv * vv.x;
                acc[kq * 4 + 1] += pv * vv.y;
                acc[kq * 4 + 2] += pv * vv.z;
                acc[kq * 4 + 3] += pv * vv.w;
            }
        }
    }

    float inv = 1.0f / row_sum;
    size_t base = (size_t)(b * 2048 + t) * 512 + h * 64;
    #pragma unroll
    for (int kq = 0; kq < 4; kq++) {
        #pragma unroll
        for (int r = 0; r < 4; r++) {
            float v = acc[kq * 4 + r] * inv;
            bf16 hv = __float2bfloat16_rn(v);
            bf16 lv = __float2bfloat16_rn(v - __bfloat162float(hv));
            ctxh[base + kq * 16 + g * 4 + r] = hv;
            ctxl[base + kq * 16 + g * 4 + r] = lv;
        }
    }
}

// ---------------- launch ----------------
extern "C" void kernel_launch(void* const* d_in, const int* in_sizes, int n_in,
                              void* d_out, int out_size) {
    const float* x     = (const float*)d_in[0];
    const float* in_w  = (const float*)d_in[1];
    const float* in_b  = (const float*)d_in[2];
    const float* out_w = (const float*)d_in[3];
    const float* out_b = (const float*)d_in[4];
    const float* ln1_g = (const float*)d_in[5];
    const float* ln1_b = (const float*)d_in[6];
    const float* ln2_g = (const float*)d_in[7];
    const float* ln2_b = (const float*)d_in[8];
    const float* w1    = (const float*)d_in[9];
    const float* b1    = (const float*)d_in[10];
    const float* w2    = (const float*)d_in[11];
    const float* b2    = (const float*)d_in[12];
    float* out = (float*)d_out;

    float* pqkv;
    bf16 *px2h, *px2l, *pctxh, *pctxl, *px3h, *px3l, *phh, *phl;
    bf16 *pwah, *pwal, *pwbh, *pwbl, *pw1h, *pw1l, *pw2h, *pw2l;
    cudaGetSymbolAddress((void**)&pqkv, g_qkv);
    cudaGetSymbolAddress((void**)&px2h, g_x2h);  cudaGetSymbolAddress((void**)&px2l, g_x2l);
    cudaGetSymbolAddress((void**)&pctxh, g_ctxh); cudaGetSymbolAddress((void**)&pctxl, g_ctxl);
    cudaGetSymbolAddress((void**)&px3h, g_x3h);  cudaGetSymbolAddress((void**)&px3l, g_x3l);
    cudaGetSymbolAddress((void**)&phh, g_hh);    cudaGetSymbolAddress((void**)&phl, g_hl);
    cudaGetSymbolAddress((void**)&pwah, g_wah);  cudaGetSymbolAddress((void**)&pwal, g_wal);
    cudaGetSymbolAddress((void**)&pwbh, g_wbh);  cudaGetSymbolAddress((void**)&pwbl, g_wbl);
    cudaGetSymbolAddress((void**)&pw1h, g_w1h);  cudaGetSymbolAddress((void**)&pw1l, g_w1l);
    cudaGetSymbolAddress((void**)&pw2h, g_w2h);  cudaGetSymbolAddress((void**)&pw2l, g_w2l);

    cudaFuncSetAttribute(gemm_mma<EPI_BIAS>,       cudaFuncAttributeMaxDynamicSharedMemorySize, GEMM_SMEM);
    cudaFuncSetAttribute(gemm_mma<EPI_BIAS_RES>,   cudaFuncAttributeMaxDynamicSharedMemorySize, GEMM_SMEM);
    cudaFuncSetAttribute(gemm_mma<EPI_GELU_SPLIT>, cudaFuncAttributeMaxDynamicSharedMemorySize, GEMM_SMEM);

    // 0) split weights
    split_kernel<<<(1536 * 512 / 4 + 255) / 256, 256>>>(in_w,  pwah, pwal, 1536 * 512 / 4);
    split_kernel<<<(512 * 512 / 4 + 255) / 256, 256>>>(out_w, pwbh, pwbl, 512 * 512 / 4);
    split_kernel<<<(2048 * 512 / 4 + 255) / 256, 256>>>(w1,    pw1h, pw1l, 2048 * 512 / 4);
    split_kernel<<<(512 * 2048 / 4 + 255) / 256, 256>>>(w2,    pw2h, pw2l, 512 * 2048 / 4);

    // 1) x2 = LN1(x)
    ln_split_kernel<<<8192, 128>>>(x, ln1_g, ln1_b, px2h, px2l);

    // 2) qkv = x2 @ in_w^T + in_b   [8192,1536]
    {
        dim3 grid(1536 / 128, 8192 / 128);
        gemm_mma<EPI_BIAS><<<grid, 256, GEMM_SMEM>>>(px2h, px2l, pwah, pwal, in_b, nullptr,
                                                     pqkv, nullptr, nullptr, 1536, 512);
    }

    // 3) ctx = attention(qkv)
    {
        dim3 grid(2048 / 64, 4 * 8);
        attn_kernel<<<grid, 256>>>(pqkv, pctxh, pctxl);
    }

    // 4) out = x + ctx @ out_w^T + out_b   [8192,512]
    {
        dim3 grid(512 / 128, 8192 / 128);
        gemm_mma<EPI_BIAS_RES><<<grid, 256, GEMM_SMEM>>>(pctxh, pctxl, pwbh, pwbl, out_b, x,
                                                         out, nullptr, nullptr, 512, 512);
    }

    // 5) x3 = LN2(out)
    ln_split_kernel<<<8192, 128>>>(out, ln2_g, ln2_b, px3h, px3l);

    // 6) h = gelu(x3 @ w1^T + b1)  [8192,2048]
    {
        dim3 grid(2048 / 128, 8192 / 128);
        gemm_mma<EPI_GELU_SPLIT><<<grid, 256, GEMM_SMEM>>>(px3h, px3l, pw1h, pw1l, b1, nullptr,
                                                           nullptr, phh, phl, 2048, 512);
    }

    // 7) out = out + h @ w2^T + b2  [8192,512]
    {
        dim3 grid(512 / 128, 8192 / 128);
        gemm_mma<EPI_BIAS_RES><<<grid, 256, GEMM_SMEM>>>(phh, phl, pw2h, pw2l, b2, out,
                                                         out, nullptr, nullptr, 512, 2048);
    }
}

// round 5
// speedup vs baseline: 2.0639x; 1.1478x over previous
#include <cuda_runtime.h>
#include <cuda_bf16.h>
#include <math.h>
#include <stdint.h>

typedef __nv_bfloat16 bf16;

// B=4, T=2048, D=512, H=8, HD=64, F=2048, WINDOW=128, rows=8192

// ---------------- scratch ----------------
__device__ float g_qkv [8192 * 1536];
__device__ bf16  g_x2h [8192 * 512],  g_x2l [8192 * 512];
__device__ bf16  g_ctxh[8192 * 512],  g_ctxl[8192 * 512];
__device__ bf16  g_x3h [8192 * 512],  g_x3l [8192 * 512];
__device__ bf16  g_hh  [8192 * 2048], g_hl  [8192 * 2048];
__device__ bf16  g_wah [1536 * 512],  g_wal [1536 * 512];
__device__ bf16  g_wbh [512 * 512],   g_wbl [512 * 512];
__device__ bf16  g_w1h [2048 * 512],  g_w1l [2048 * 512];
__device__ bf16  g_w2h [512 * 2048],  g_w2l [512 * 2048];

// ---------------- helpers ----------------
__device__ __forceinline__ uint32_t smem_u32(const void* p) {
    uint32_t a;
    asm("{ .reg .u64 t; cvta.to.shared.u64 t, %1; cvt.u32.u64 %0, t; }" : "=r"(a) : "l"(p));
    return a;
}
__device__ __forceinline__ void cp16(uint32_t d, const void* g) {
    asm volatile("cp.async.cg.shared.global [%0], [%1], 16;" :: "r"(d), "l"(g));
}
#define CP_COMMIT() asm volatile("cp.async.commit_group;" ::: "memory")
#define CP_WAIT(n)  asm volatile("cp.async.wait_group %0;" :: "n"(n) : "memory")

#define LDSM4(r, addr) \
    asm volatile("ldmatrix.sync.aligned.m8n8.x4.shared.b16 {%0,%1,%2,%3}, [%4];" \
        : "=r"((r)[0]), "=r"((r)[1]), "=r"((r)[2]), "=r"((r)[3]) : "r"(addr))

#define MMA16816(c, a, b) \
    asm volatile("mma.sync.aligned.m16n8k16.row.col.f32.bf16.bf16.f32 " \
        "{%0,%1,%2,%3}, {%4,%5,%6,%7}, {%8,%9}, {%0,%1,%2,%3};" \
        : "+f"((c)[0]), "+f"((c)[1]), "+f"((c)[2]), "+f"((c)[3]) \
        : "r"((a)[0]), "r"((a)[1]), "r"((a)[2]), "r"((a)[3]), "r"((b)[0]), "r"((b)[1]))

// ---------------- weight split: fp32 -> (hi, lo) bf16 ----------------
__global__ void split_kernel(const float* __restrict__ w, bf16* __restrict__ hi,
                             bf16* __restrict__ lo, int n4) {
    int i = blockIdx.x * 256 + threadIdx.x;
    if (i >= n4) return;
    float4 v = *(const float4*)(w + i * 4);
    bf16 h0 = __float2bfloat16_rn(v.x), h1 = __float2bfloat16_rn(v.y);
    bf16 h2 = __float2bfloat16_rn(v.z), h3 = __float2bfloat16_rn(v.w);
    bf16 l0 = __float2bfloat16_rn(v.x - __bfloat162float(h0));
    bf16 l1 = __float2bfloat16_rn(v.y - __bfloat162float(h1));
    bf16 l2 = __float2bfloat16_rn(v.z - __bfloat162float(h2));
    bf16 l3 = __float2bfloat16_rn(v.w - __bfloat162float(h3));
    __nv_bfloat162 ha = {h0, h1}, hb = {h2, h3}, la = {l0, l1}, lb = {l2, l3};
    *(__nv_bfloat162*)(hi + i * 4)     = ha;
    *(__nv_bfloat162*)(hi + i * 4 + 2) = hb;
    *(__nv_bfloat162*)(lo + i * 4)     = la;
    *(__nv_bfloat162*)(lo + i * 4 + 2) = lb;
}

// ---------------- LayerNorm with split output ----------------
__global__ void ln_split_kernel(const float* __restrict__ x, const float* __restrict__ gw,
                                const float* __restrict__ bw, bf16* __restrict__ hi,
                                bf16* __restrict__ lo) {
    int row = blockIdx.x;
    int t = threadIdx.x;
    const float* xr = x + (size_t)row * 512;
    float4 v = *(const float4*)(xr + t * 4);
    float s  = v.x + v.y + v.z + v.w;
    float sq = v.x * v.x + v.y * v.y + v.z * v.z + v.w * v.w;
    #pragma unroll
    for (int o = 16; o > 0; o >>= 1) {
        s  += __shfl_xor_sync(0xffffffffu, s,  o);
        sq += __shfl_xor_sync(0xffffffffu, sq, o);
    }
    __shared__ float red[8];
    int wid = t >> 5, lane = t & 31;
    if (lane == 0) { red[wid] = s; red[4 + wid] = sq; }
    __syncthreads();
    float S  = red[0] + red[1] + red[2] + red[3];
    float SQ = red[4] + red[5] + red[6] + red[7];
    float mu   = S * (1.0f / 512.0f);
    float var  = SQ * (1.0f / 512.0f) - mu * mu;
    float rstd = rsqrtf(var + 1e-5f);
    float4 gv = *(const float4*)(gw + t * 4);
    float4 bv = *(const float4*)(bw + t * 4);
    float o0 = (v.x - mu) * rstd * gv.x + bv.x;
    float o1 = (v.y - mu) * rstd * gv.y + bv.y;
    float o2 = (v.z - mu) * rstd * gv.z + bv.z;
    float o3 = (v.w - mu) * rstd * gv.w + bv.w;
    bf16 h0 = __float2bfloat16_rn(o0), h1 = __float2bfloat16_rn(o1);
    bf16 h2 = __float2bfloat16_rn(o2), h3 = __float2bfloat16_rn(o3);
    bf16 l0 = __float2bfloat16_rn(o0 - __bfloat162float(h0));
    bf16 l1 = __float2bfloat16_rn(o1 - __bfloat162float(h1));
    bf16 l2 = __float2bfloat16_rn(o2 - __bfloat162float(h2));
    bf16 l3 = __float2bfloat16_rn(o3 - __bfloat162float(h3));
    size_t base = (size_t)row * 512 + t * 4;
    __nv_bfloat162 ha = {h0, h1}, hb = {h2, h3}, la = {l0, l1}, lb = {l2, l3};
    *(__nv_bfloat162*)(hi + base)     = ha;
    *(__nv_bfloat162*)(hi + base + 2) = hb;
    *(__nv_bfloat162*)(lo + base)     = la;
    *(__nv_bfloat162*)(lo + base + 2) = lb;
}

// ---------------- mma.sync GEMM: C[M,N] = A[M,K] @ W[N,K]^T (3-term bf16 split) ----------------
// CTA tile 128x128, 4 warps of 64x64, BK=32 bf16, 2-stage cp.async (2 CTAs/SM).
// MMA:LDSM ratio 6:1 (192 MMA / 32 ldsm.x4 per warp per K-block).
#define EPI_BIAS       0
#define EPI_BIAS_RES   1
#define EPI_GELU_SPLIT 2

#define TPAD     80              // bytes per smem row (32 bf16 + 8 pad)
#define TILE_B   (128 * TPAD)    // 10240
#define STAGE_B  (4 * TILE_B)    // 40960
#define NSTAGE   2
#define GEMM_SMEM (NSTAGE * STAGE_B)

template<int EPI>
__global__ __launch_bounds__(128)
void gemm_mma(const bf16* __restrict__ Ah, const bf16* __restrict__ Al,
              const bf16* __restrict__ Bh, const bf16* __restrict__ Bl,
              const float* __restrict__ bias, const float* __restrict__ res,
              float* __restrict__ Cf, bf16* __restrict__ Ch, bf16* __restrict__ Cl,
              int N, int K) {
    extern __shared__ char sm[];
    const int tid = threadIdx.x;
    const int lane = tid & 31, wid = tid >> 5;       // 4 warps
    const int wm = wid & 1, wn = wid >> 1;           // warp 64x64 tile
    const int m0 = blockIdx.y * 128, n0 = blockIdx.x * 128;
    const uint32_t sbase = smem_u32(sm);

    const bf16* srcs[4] = { Ah + (size_t)m0 * K, Al + (size_t)m0 * K,
                            Bh + (size_t)n0 * K, Bl + (size_t)n0 * K };

    // one stage = 4 tiles of 128 rows x 32 bf16
    auto load_stage = [&](int s, int kb) {
        uint32_t so = sbase + (uint32_t)s * STAGE_B;
        #pragma unroll
        for (int tt = 0; tt < 4; tt++) {
            const bf16* gp = srcs[tt] + kb * 32;
            uint32_t tb = so + tt * TILE_B;
            #pragma unroll
            for (int it = 0; it < 4; it++) {
                int idx = tid + it * 128;          // 0..511
                int r = idx >> 2, c = idx & 3;
                cp16(tb + r * TPAD + c * 16, gp + (size_t)r * K + c * 8);
            }
        }
    };

    float acc[4][8][4];
    #pragma unroll
    for (int i = 0; i < 4; i++)
        #pragma unroll
        for (int j = 0; j < 8; j++)
            #pragma unroll
            for (int r = 0; r < 4; r++) acc[i][j][r] = 0.0f;

    const int nkb = K >> 5;
    load_stage(0, 0);
    CP_COMMIT();

    const uint32_t aRow = wm * 64 + (lane & 15);
    const uint32_t aChunkHalf = (lane >> 4);
    const uint32_t bRow = wn * 64 + (lane & 7) + ((lane >> 4) << 3);
    const uint32_t bChunkHalf = (lane >> 3) & 1;

    for (int kb = 0; kb < nkb; kb++) {
        bool more = (kb + 1) < nkb;
        if (more) { load_stage((kb + 1) & 1, kb + 1); CP_COMMIT(); CP_WAIT(1); }
        else      { CP_WAIT(0); }
        __syncthreads();

        uint32_t so = sbase + (uint32_t)(kb & 1) * STAGE_B;
        #pragma unroll
        for (int ks = 0; ks < 2; ks++) {
            uint32_t Ahf[4][4], Alf[4][4];
            #pragma unroll
            for (int i = 0; i < 4; i++) {
                uint32_t off = (aRow + i * 16) * TPAD + (ks * 2 + aChunkHalf) * 16;
                LDSM4(Ahf[i], so + off);
                LDSM4(Alf[i], so + TILE_B + off);
            }
            uint32_t Bhf[4][4], Blf[4][4];
            #pragma unroll
            for (int jp = 0; jp < 4; jp++) {
                uint32_t off = (bRow + jp * 16) * TPAD + (ks * 2 + bChunkHalf) * 16;
                LDSM4(Bhf[jp], so + 2 * TILE_B + off);
                LDSM4(Blf[jp], so + 3 * TILE_B + off);
            }
            #pragma unroll
            for (int i = 0; i < 4; i++) {
                #pragma unroll
                for (int j = 0; j < 8; j++) {
                    int jp = j >> 1, jo = (j & 1) * 2;
                    MMA16816(acc[i][j], Ahf[i], (Bhf[jp] + jo));
                    MMA16816(acc[i][j], Ahf[i], (Blf[jp] + jo));
                    MMA16816(acc[i][j], Alf[i], (Bhf[jp] + jo));
                }
            }
        }
        __syncthreads();
    }

    // ---------------- epilogue ----------------
    #pragma unroll
    for (int i = 0; i < 4; i++) {
        int rb = m0 + wm * 64 + i * 16 + (lane >> 2);
        #pragma unroll
        for (int j = 0; j < 8; j++) {
            int col = n0 + wn * 64 + j * 8 + (lane & 3) * 2;
            float b0 = bias[col], b1 = bias[col + 1];
            #pragma unroll
            for (int half = 0; half < 2; half++) {
                int row = rb + half * 8;
                float o0 = acc[i][j][half * 2 + 0] + b0;
                float o1 = acc[i][j][half * 2 + 1] + b1;
                size_t ob = (size_t)row * N + col;
                if (EPI == EPI_BIAS_RES) {
                    float2 rv = *(const float2*)(res + ob);
                    o0 += rv.x; o1 += rv.y;
                }
                if (EPI == EPI_GELU_SPLIT) {
                    o0 = 0.5f * o0 * (1.0f + erff(o0 * 0.70710678118654752f));
                    o1 = 0.5f * o1 * (1.0f + erff(o1 * 0.70710678118654752f));
                    bf16 h0 = __float2bfloat16_rn(o0), h1 = __float2bfloat16_rn(o1);
                    bf16 l0 = __float2bfloat16_rn(o0 - __bfloat162float(h0));
                    bf16 l1 = __float2bfloat16_rn(o1 - __bfloat162float(h1));
                    __nv_bfloat162 hv = {h0, h1}, lv = {l0, l1};
                    *(__nv_bfloat162*)(Ch + ob) = hv;
                    *(__nv_bfloat162*)(Cl + ob) = lv;
                } else {
                    float2 o = make_float2(o0, o1);
                    *(float2*)(Cf + ob) = o;
                }
            }
        }
    }
}

// ---------------- Sliding-window attention (fp32 SIMT, split output) ----------------
__global__ __launch_bounds__(256)
void attn_kernel(const float* __restrict__ qkv, bf16* __restrict__ ctxh, bf16* __restrict__ ctxl) {
    __shared__ float Qs[64][65];
    __shared__ float Ks[32][65];
    __shared__ __align__(16) float Vs[32][64];
    __shared__ float Ps[64][33];

    int bh = blockIdx.y;
    int b = bh >> 3, h = bh & 7;
    int t0 = blockIdx.x * 64;
    int tid = threadIdx.x;
    int q = tid >> 2, g = tid & 3;
    const float scale = 0.125f;

    for (int i = tid; i < 64 * 16; i += 256) {
        int r = i >> 4, c4 = (i & 15) << 2;
        float4 v = *(const float4*)(qkv + (size_t)(b * 2048 + t0 + r) * 1536 + h * 64 + c4);
        Qs[r][c4 + 0] = v.x * scale;
        Qs[r][c4 + 1] = v.y * scale;
        Qs[r][c4 + 2] = v.z * scale;
        Qs[r][c4 + 3] = v.w * scale;
    }

    float acc[16];
    #pragma unroll
    for (int i = 0; i < 16; i++) acc[i] = 0.0f;
    float row_max = -1e30f, row_sum = 0.0f;
    int t = t0 + q;

    for (int c = 0; c < 6; c++) {
        int kbase = t0 - 128 + c * 32;
        if (kbase + 31 < 0) continue;
        __syncthreads();
        for (int i = tid; i < 32 * 16; i += 256) {
            int r = i >> 4, c4 = (i & 15) << 2;
            int s = kbase + r;
            float4 kv = make_float4(0.f, 0.f, 0.f, 0.f);
            float4 vv = make_float4(0.f, 0.f, 0.f, 0.f);
            if (s >= 0) {
                size_t base = (size_t)(b * 2048 + s) * 1536 + h * 64 + c4;
                kv = *(const float4*)(qkv + base + 512);
                vv = *(const float4*)(qkv + base + 1024);
            }
            Ks[r][c4 + 0] = kv.x; Ks[r][c4 + 1] = kv.y; Ks[r][c4 + 2] = kv.z; Ks[r][c4 + 3] = kv.w;
            *(float4*)&Vs[r][c4] = vv;
        }
        __syncthreads();

        float sc[8];
        #pragma unroll
        for (int j = 0; j < 8; j++) sc[j] = 0.0f;
        #pragma unroll 16
        for (int d = 0; d < 64; d++) {
            float qv = Qs[q][d];
            #pragma unroll
            for (int j = 0; j < 8; j++) sc[j] += qv * Ks[g * 8 + j][d];
        }
        float cmax = -1e30f;
        bool al[8];
        #pragma unroll
        for (int j = 0; j < 8; j++) {
            int s = kbase + g * 8 + j;
            al[j] = (s >= 0) && (s <= t) && (s >= t - 127);
            if (!al[j]) sc[j] = -1e30f;
            cmax = fmaxf(cmax, sc[j]);
        }
        cmax = fmaxf(cmax, __shfl_xor_sync(0xffffffffu, cmax, 1));
        cmax = fmaxf(cmax, __shfl_xor_sync(0xffffffffu, cmax, 2));
        float nm = fmaxf(row_max, cmax);
        float corr = __expf(row_max - nm);
        float p[8];
        float csum = 0.0f;
        #pragma unroll
        for (int j = 0; j < 8; j++) {
            p[j] = al[j] ? __expf(sc[j] - nm) : 0.0f;
            csum += p[j];
        }
        csum += __shfl_xor_sync(0xffffffffu, csum, 1);
        csum += __shfl_xor_sync(0xffffffffu, csum, 2);
        row_sum = row_sum * corr + csum;
        #pragma unroll
        for (int i = 0; i < 16; i++) acc[i] *= corr;
        row_max = nm;
        #pragma unroll
        for (int j = 0; j < 8; j++) Ps[q][g * 8 + j] = p[j];
        __syncthreads();

        #pragma unroll 4
        for (int s = 0; s < 32; s++) {
            float pv = Ps[q][s];
            #pragma unroll
            for (int kq = 0; kq < 4; kq++) {
                float4 vv = *(const float4*)&Vs[s][kq * 16 + g * 4];
                acc[kq * 4 + 0] += pv * vv.x;
                acc[kq * 4 + 1] += pv * vv.y;
                acc[kq * 4 + 2] += pv * vv.z;
                acc[kq * 4 + 3] += pv * vv.w;
            }
        }
    }

    float inv = 1.0f / row_sum;
    size_t base = (size_t)(b * 2048 + t) * 512 + h * 64;
    #pragma unroll
    for (int kq = 0; kq < 4; kq++) {
        #pragma unroll
        for (int r = 0; r < 4; r++) {
            float v = acc[kq * 4 + r] * inv;
            bf16 hv = __float2bfloat16_rn(v);
            bf16 lv = __float2bfloat16_rn(v - __bfloat162float(hv));
            ctxh[base + kq * 16 + g * 4 + r] = hv;
            ctxl[base + kq * 16 + g * 4 + r] = lv;
        }
    }
}

// ---------------- launch ----------------
extern "C" void kernel_launch(void* const* d_in, const int* in_sizes, int n_in,
                              void* d_out, int out_size) {
    const float* x     = (const float*)d_in[0];
    const float* in_w  = (const float*)d_in[1];
    const float* in_b  = (const float*)d_in[2];
    const float* out_w = (const float*)d_in[3];
    const float* out_b = (const float*)d_in[4];
    const float* ln1_g = (const float*)d_in[5];
    const float* ln1_b = (const float*)d_in[6];
    const float* ln2_g = (const float*)d_in[7];
    const float* ln2_b = (const float*)d_in[8];
    const float* w1    = (const float*)d_in[9];
    const float* b1    = (const float*)d_in[10];
    const float* w2    = (const float*)d_in[11];
    const float* b2    = (const float*)d_in[12];
    float* out = (float*)d_out;

    float* pqkv;
    bf16 *px2h, *px2l, *pctxh, *pctxl, *px3h, *px3l, *phh, *phl;
    bf16 *pwah, *pwal, *pwbh, *pwbl, *pw1h, *pw1l, *pw2h, *pw2l;
    cudaGetSymbolAddress((void**)&pqkv, g_qkv);
    cudaGetSymbolAddress((void**)&px2h, g_x2h);  cudaGetSymbolAddress((void**)&px2l, g_x2l);
    cudaGetSymbolAddress((void**)&pctxh, g_ctxh); cudaGetSymbolAddress((void**)&pctxl, g_ctxl);
    cudaGetSymbolAddress((void**)&px3h, g_x3h);  cudaGetSymbolAddress((void**)&px3l, g_x3l);
    cudaGetSymbolAddress((void**)&phh, g_hh);    cudaGetSymbolAddress((void**)&phl, g_hl);
    cudaGetSymbolAddress((void**)&pwah, g_wah);  cudaGetSymbolAddress((void**)&pwal, g_wal);
    cudaGetSymbolAddress((void**)&pwbh, g_wbh);  cudaGetSymbolAddress((void**)&pwbl, g_wbl);
    cudaGetSymbolAddress((void**)&pw1h, g_w1h);  cudaGetSymbolAddress((void**)&pw1l, g_w1l);
    cudaGetSymbolAddress((void**)&pw2h, g_w2h);  cudaGetSymbolAddress((void**)&pw2l, g_w2l);

    cudaFuncSetAttribute(gemm_mma<EPI_BIAS>,       cudaFuncAttributeMaxDynamicSharedMemorySize, GEMM_SMEM);
    cudaFuncSetAttribute(gemm_mma<EPI_BIAS_RES>,   cudaFuncAttributeMaxDynamicSharedMemorySize, GEMM_SMEM);
    cudaFuncSetAttribute(gemm_mma<EPI_GELU_SPLIT>, cudaFuncAttributeMaxDynamicSharedMemorySize, GEMM_SMEM);

    // 0) split weights
    split_kernel<<<(1536 * 512 / 4 + 255) / 256, 256>>>(in_w,  pwah, pwal, 1536 * 512 / 4);
    split_kernel<<<(512 * 512 / 4 + 255) / 256, 256>>>(out_w, pwbh, pwbl, 512 * 512 / 4);
    split_kernel<<<(2048 * 512 / 4 + 255) / 256, 256>>>(w1,    pw1h, pw1l, 2048 * 512 / 4);
    split_kernel<<<(512 * 2048 / 4 + 255) / 256, 256>>>(w2,    pw2h, pw2l, 512 * 2048 / 4);

    // 1) x2 = LN1(x)
    ln_split_kernel<<<8192, 128>>>(x, ln1_g, ln1_b, px2h, px2l);

    // 2) qkv = x2 @ in_w^T + in_b   [8192,1536]
    {
        dim3 grid(1536 / 128, 8192 / 128);
        gemm_mma<EPI_BIAS><<<grid, 128, GEMM_SMEM>>>(px2h, px2l, pwah, pwal, in_b, nullptr,
                                                     pqkv, nullptr, nullptr, 1536, 512);
    }

    // 3) ctx = attention(qkv)
    {
        dim3 grid(2048 / 64, 4 * 8);
        attn_kernel<<<grid, 256>>>(pqkv, pctxh, pctxl);
    }

    // 4) out = x + ctx @ out_w^T + out_b   [8192,512]
    {
        dim3 grid(512 / 128, 8192 / 128);
        gemm_mma<EPI_BIAS_RES><<<grid, 128, GEMM_SMEM>>>(pctxh, pctxl, pwbh, pwbl, out_b, x,
                                                         out, nullptr, nullptr, 512, 512);
    }

    // 5) x3 = LN2(out)
    ln_split_kernel<<<8192, 128>>>(out, ln2_g, ln2_b, px3h, px3l);

    // 6) h = gelu(x3 @ w1^T + b1)  [8192,2048]
    {
        dim3 grid(2048 / 128, 8192 / 128);
        gemm_mma<EPI_GELU_SPLIT><<<grid, 128, GEMM_SMEM>>>(px3h, px3l, pw1h, pw1l, b1, nullptr,
                                                           nullptr, phh, phl, 2048, 512);
    }

    // 7) out = out + h @ w2^T + b2  [8192,512]
    {
        dim3 grid(512 / 128, 8192 / 128);
        gemm_mma<EPI_BIAS_RES><<<grid, 128, GEMM_SMEM>>>(phh, phl, pw2h, pw2l, b2, out,
                                                         out, nullptr, nullptr, 512, 2048);
    }
}

// round 7
// speedup vs baseline: 2.5890x; 1.2544x over previous
#include <cuda_runtime.h>
#include <cuda_bf16.h>
#include <math.h>
#include <stdint.h>

typedef __nv_bfloat16 bf16;

// B=4, T=2048, D=512, H=8, HD=64, F=2048, WINDOW=128, rows=8192

// ---------------- scratch ----------------
__device__ bf16  g_qh [32 * 2048 * 64], g_ql [32 * 2048 * 64];   // [bh][t][d], scaled
__device__ bf16  g_kh [32 * 2048 * 64], g_kl [32 * 2048 * 64];   // [bh][t][d]
__device__ bf16  g_vth[32 * 64 * 2048], g_vtl[32 * 64 * 2048];   // [bh][d][t]
__device__ bf16  g_x2h [8192 * 512],  g_x2l [8192 * 512];
__device__ bf16  g_ctxh[8192 * 512],  g_ctxl[8192 * 512];
__device__ bf16  g_x3h [8192 * 512],  g_x3l [8192 * 512];
__device__ bf16  g_hh  [8192 * 2048], g_hl  [8192 * 2048];
__device__ bf16  g_wah [1536 * 512],  g_wal [1536 * 512];
__device__ bf16  g_wbh [512 * 512],   g_wbl [512 * 512];
__device__ bf16  g_w1h [2048 * 512],  g_w1l [2048 * 512];
__device__ bf16  g_w2h [512 * 2048],  g_w2l [512 * 2048];

// ---------------- helpers ----------------
__device__ __forceinline__ uint32_t smem_u32(const void* p) {
    uint32_t a;
    asm("{ .reg .u64 t; cvta.to.shared.u64 t, %1; cvt.u32.u64 %0, t; }" : "=r"(a) : "l"(p));
    return a;
}
__device__ __forceinline__ void cp16(uint32_t d, const void* g) {
    asm volatile("cp.async.cg.shared.global [%0], [%1], 16;" :: "r"(d), "l"(g));
}
__device__ __forceinline__ void cp16z(uint32_t d, const void* g, uint32_t srcsz) {
    asm volatile("cp.async.cg.shared.global [%0], [%1], 16, %2;" :: "r"(d), "l"(g), "r"(srcsz));
}
#define CP_COMMIT() asm volatile("cp.async.commit_group;" ::: "memory")
#define CP_WAIT(n)  asm volatile("cp.async.wait_group %0;" :: "n"(n) : "memory")

#define LDSM4(r, addr) \
    asm volatile("ldmatrix.sync.aligned.m8n8.x4.shared.b16 {%0,%1,%2,%3}, [%4];" \
        : "=r"((r)[0]), "=r"((r)[1]), "=r"((r)[2]), "=r"((r)[3]) : "r"(addr))

#define MMA16816(c, a, b) \
    asm volatile("mma.sync.aligned.m16n8k16.row.col.f32.bf16.bf16.f32 " \
        "{%0,%1,%2,%3}, {%4,%5,%6,%7}, {%8,%9}, {%0,%1,%2,%3};" \
        : "+f"((c)[0]), "+f"((c)[1]), "+f"((c)[2]), "+f"((c)[3]) \
        : "r"((a)[0]), "r"((a)[1]), "r"((a)[2]), "r"((a)[3]), "r"((b)[0]), "r"((b)[1]))

__device__ __forceinline__ void split2(float a, float b, bf16* hp, bf16* lp) {
    bf16 h0 = __float2bfloat16_rn(a), h1 = __float2bfloat16_rn(b);
    bf16 l0 = __float2bfloat16_rn(a - __bfloat162float(h0));
    bf16 l1 = __float2bfloat16_rn(b - __bfloat162float(h1));
    __nv_bfloat162 hv = {h0, h1}, lv = {l0, l1};
    *(__nv_bfloat162*)hp = hv;
    *(__nv_bfloat162*)lp = lv;
}

// ---------------- weight split ----------------
__global__ void split_kernel(const float* __restrict__ w, bf16* __restrict__ hi,
                             bf16* __restrict__ lo, int n4) {
    int i = blockIdx.x * 256 + threadIdx.x;
    if (i >= n4) return;
    float4 v = *(const float4*)(w + i * 4);
    split2(v.x, v.y, hi + i * 4, lo + i * 4);
    split2(v.z, v.w, hi + i * 4 + 2, lo + i * 4 + 2);
}

// ---------------- LayerNorm with split output ----------------
__global__ void ln_split_kernel(const float* __restrict__ x, const float* __restrict__ gw,
                                const float* __restrict__ bw, bf16* __restrict__ hi,
                                bf16* __restrict__ lo) {
    int row = blockIdx.x;
    int t = threadIdx.x;
    const float* xr = x + (size_t)row * 512;
    float4 v = *(const float4*)(xr + t * 4);
    float s  = v.x + v.y + v.z + v.w;
    float sq = v.x * v.x + v.y * v.y + v.z * v.z + v.w * v.w;
    #pragma unroll
    for (int o = 16; o > 0; o >>= 1) {
        s  += __shfl_xor_sync(0xffffffffu, s,  o);
        sq += __shfl_xor_sync(0xffffffffu, sq, o);
    }
    __shared__ float red[8];
    int wid = t >> 5, lane = t & 31;
    if (lane == 0) { red[wid] = s; red[4 + wid] = sq; }
    __syncthreads();
    float S  = red[0] + red[1] + red[2] + red[3];
    float SQ = red[4] + red[5] + red[6] + red[7];
    float mu   = S * (1.0f / 512.0f);
    float var  = SQ * (1.0f / 512.0f) - mu * mu;
    float rstd = rsqrtf(var + 1e-5f);
    float4 gv = *(const float4*)(gw + t * 4);
    float4 bv = *(const float4*)(bw + t * 4);
    float o0 = (v.x - mu) * rstd * gv.x + bv.x;
    float o1 = (v.y - mu) * rstd * gv.y + bv.y;
    float o2 = (v.z - mu) * rstd * gv.z + bv.z;
    float o3 = (v.w - mu) * rstd * gv.w + bv.w;
    size_t base = (size_t)row * 512 + t * 4;
    split2(o0, o1, hi + base, lo + base);
    split2(o2, o3, hi + base + 2, lo + base + 2);
}

// ---------------- mma.sync GEMM (3-term bf16 split) ----------------
#define EPI_BIAS       0
#define EPI_BIAS_RES   1
#define EPI_GELU_SPLIT 2
#define EPI_QKV        3

#define TPAD     80
#define TILE_B   (128 * TPAD)
#define STAGE_B  (4 * TILE_B)
#define NSTAGE   2
#define GEMM_SMEM (NSTAGE * STAGE_B)

template<int EPI>
__global__ __launch_bounds__(128)
void gemm_mma(const bf16* __restrict__ Ah, const bf16* __restrict__ Al,
              const bf16* __restrict__ Bh, const bf16* __restrict__ Bl,
              const float* __restrict__ bias, const float* __restrict__ res,
              float* __restrict__ Cf, bf16* __restrict__ Ch, bf16* __restrict__ Cl,
              bf16* __restrict__ Kh, bf16* __restrict__ Kl,
              bf16* __restrict__ Vth, bf16* __restrict__ Vtl,
              int N, int K) {
    extern __shared__ char sm[];
    const int tid = threadIdx.x;
    const int lane = tid & 31, wid = tid >> 5;
    const int wm = wid & 1, wn = wid >> 1;
    const int m0 = blockIdx.y * 128, n0 = blockIdx.x * 128;
    const uint32_t sbase = smem_u32(sm);

    const bf16* srcs[4] = { Ah + (size_t)m0 * K, Al + (size_t)m0 * K,
                            Bh + (size_t)n0 * K, Bl + (size_t)n0 * K };

    auto load_stage = [&](int s, int kb) {
        uint32_t so = sbase + (uint32_t)s * STAGE_B;
        #pragma unroll
        for (int tt = 0; tt < 4; tt++) {
            const bf16* gp = srcs[tt] + kb * 32;
            uint32_t tb = so + tt * TILE_B;
            #pragma unroll
            for (int it = 0; it < 4; it++) {
                int idx = tid + it * 128;
                int r = idx >> 2, c = idx & 3;
                cp16(tb + r * TPAD + c * 16, gp + (size_t)r * K + c * 8);
            }
        }
    };

    float acc[4][8][4];
    #pragma unroll
    for (int i = 0; i < 4; i++)
        #pragma unroll
        for (int j = 0; j < 8; j++)
            #pragma unroll
            for (int r = 0; r < 4; r++) acc[i][j][r] = 0.0f;

    const int nkb = K >> 5;
    load_stage(0, 0);
    CP_COMMIT();

    const uint32_t aRow = wm * 64 + (lane & 15);
    const uint32_t aChunkHalf = (lane >> 4);
    const uint32_t bRow = wn * 64 + (lane & 7) + ((lane >> 4) << 3);
    const uint32_t bChunkHalf = (lane >> 3) & 1;

    for (int kb = 0; kb < nkb; kb++) {
        bool more = (kb + 1) < nkb;
        if (more) { load_stage((kb + 1) & 1, kb + 1); CP_COMMIT(); CP_WAIT(1); }
        else      { CP_WAIT(0); }
        __syncthreads();

        uint32_t so = sbase + (uint32_t)(kb & 1) * STAGE_B;
        #pragma unroll
        for (int ks = 0; ks < 2; ks++) {
            uint32_t Ahf[4][4], Alf[4][4];
            #pragma unroll
            for (int i = 0; i < 4; i++) {
                uint32_t off = (aRow + i * 16) * TPAD + (ks * 2 + aChunkHalf) * 16;
                LDSM4(Ahf[i], so + off);
                LDSM4(Alf[i], so + TILE_B + off);
            }
            uint32_t Bhf[4][4], Blf[4][4];
            #pragma unroll
            for (int jp = 0; jp < 4; jp++) {
                uint32_t off = (bRow + jp * 16) * TPAD + (ks * 2 + bChunkHalf) * 16;
                LDSM4(Bhf[jp], so + 2 * TILE_B + off);
                LDSM4(Blf[jp], so + 3 * TILE_B + off);
            }
            #pragma unroll
            for (int i = 0; i < 4; i++) {
                #pragma unroll
                for (int j = 0; j < 8; j++) {
                    int jp = j >> 1, jo = (j & 1) * 2;
                    MMA16816(acc[i][j], Ahf[i], (Bhf[jp] + jo));
                    MMA16816(acc[i][j], Ahf[i], (Blf[jp] + jo));
                    MMA16816(acc[i][j], Alf[i], (Bhf[jp] + jo));
                }
            }
        }
        __syncthreads();
    }

    // ---------------- epilogue ----------------
    #pragma unroll
    for (int i = 0; i < 4; i++) {
        int rb = m0 + wm * 64 + i * 16 + (lane >> 2);
        #pragma unroll
        for (int j = 0; j < 8; j++) {
            int col = n0 + wn * 64 + j * 8 + (lane & 3) * 2;
            float b0 = bias[col], b1 = bias[col + 1];
            #pragma unroll
            for (int half = 0; half < 2; half++) {
                int row = rb + half * 8;
                float o0 = acc[i][j][half * 2 + 0] + b0;
                float o1 = acc[i][j][half * 2 + 1] + b1;
                if (EPI == EPI_QKV) {
                    int b = row >> 11, t = row & 2047;
                    if (col < 512) {
                        int h = col >> 6, d = col & 63;
                        size_t ob = ((size_t)(b * 8 + h) * 2048 + t) * 64 + d;
                        split2(o0 * 0.125f, o1 * 0.125f, Ch + ob, Cl + ob);
                    } else if (col < 1024) {
                        int c = col - 512;
                        int h = c >> 6, d = c & 63;
                        size_t ob = ((size_t)(b * 8 + h) * 2048 + t) * 64 + d;
                        split2(o0, o1, Kh + ob, Kl + ob);
                    } else {
                        int c = col - 1024;
                        int h = c >> 6, d = c & 63;
                        size_t ob = ((size_t)(b * 8 + h) * 64 + d) * 2048 + t;
                        bf16 h0 = __float2bfloat16_rn(o0), h1 = __float2bfloat16_rn(o1);
                        Vth[ob] = h0;          Vth[ob + 2048] = h1;
                        Vtl[ob] = __float2bfloat16_rn(o0 - __bfloat162float(h0));
                        Vtl[ob + 2048] = __float2bfloat16_rn(o1 - __bfloat162float(h1));
                    }
                    continue;
                }
                size_t ob = (size_t)row * N + col;
                if (EPI == EPI_BIAS_RES) {
                    float2 rv = *(const float2*)(res + ob);
                    o0 += rv.x; o1 += rv.y;
                }
                if (EPI == EPI_GELU_SPLIT) {
                    o0 = 0.5f * o0 * (1.0f + erff(o0 * 0.70710678118654752f));
                    o1 = 0.5f * o1 * (1.0f + erff(o1 * 0.70710678118654752f));
                    split2(o0, o1, Ch + ob, Cl + ob);
                } else {
                    float2 o = make_float2(o0, o1);
                    *(float2*)(Cf + ob) = o;
                }
            }
        }
    }
}

// ---------------- mma attention ----------------
// block = (qtile 64, bh). keys = [t0-128, t0+63] = 192. 256 threads / 8 warps.
#define AQ_H   0u          // Q hi: 64 rows x 144
#define AQ_L   9216u
#define AK_H   18432u      // K hi: 192 rows x 144   (S fp32 overlays here later)
#define AK_L   46080u
#define AV_H   73728u      // VT hi: 64 rows x 400
#define AV_L   99328u
#define AP_H   124928u     // P hi: 64 rows x 400
#define AP_L   150528u
#define AS_OFF 18432u      // S fp32: 64 rows x 800 (over K region)
#define ASUM   176128u
#define ATT_SMEM 176384u

__global__ __launch_bounds__(256)
void attn_mma(const bf16* __restrict__ qh, const bf16* __restrict__ ql,
              const bf16* __restrict__ kh, const bf16* __restrict__ kl,
              const bf16* __restrict__ vth, const bf16* __restrict__ vtl,
              bf16* __restrict__ ctxh, bf16* __restrict__ ctxl) {
    extern __shared__ char sm[];
    const uint32_t sb = smem_u32(sm);
    const int tid = threadIdx.x;
    const int lane = tid & 31, wid = tid >> 5;
    const int bh = blockIdx.y;
    const int t0 = blockIdx.x * 64;
    const int kbase = t0 - 128;

    // ---- loads ----
    {
        #pragma unroll
        for (int cpi = 0; cpi < 2; cpi++) {
            const bf16* src = cpi ? ql : qh;
            uint32_t dst = sb + (cpi ? AQ_L : AQ_H);
            #pragma unroll
            for (int it = 0; it < 2; it++) {
                int idx = tid + it * 256;
                int r = idx >> 3, c = idx & 7;
                cp16(dst + r * 144 + c * 16, src + ((size_t)bh * 2048 + t0 + r) * 64 + c * 8);
            }
        }
        #pragma unroll
        for (int cpi = 0; cpi < 2; cpi++) {
            const bf16* src = cpi ? kl : kh;
            uint32_t dst = sb + (cpi ? AK_L : AK_H);
            #pragma unroll
            for (int it = 0; it < 6; it++) {
                int idx = tid + it * 256;
                int r = idx >> 3, c = idx & 7;
                int s = kbase + r;
                uint32_t sz = (s >= 0) ? 16u : 0u;
                int sc = s < 0 ? 0 : s;
                cp16z(dst + r * 144 + c * 16, src + ((size_t)bh * 2048 + sc) * 64 + c * 8, sz);
            }
        }
        #pragma unroll
        for (int cpi = 0; cpi < 2; cpi++) {
            const bf16* src = cpi ? vtl : vth;
            uint32_t dst = sb + (cpi ? AV_L : AV_H);
            #pragma unroll
            for (int it = 0; it < 6; it++) {
                int idx = tid + it * 256;
                int r = idx / 24, c = idx - r * 24;
                int scol = kbase + c * 8;
                uint32_t sz = (scol >= 0) ? 16u : 0u;
                int sc = scol < 0 ? 0 : scol;
                cp16z(dst + r * 400 + c * 16, src + ((size_t)bh * 64 + r) * 2048 + sc, sz);
            }
        }
    }
    CP_COMMIT();
    CP_WAIT(0);
    __syncthreads();

    // ---- phase 1: S = Q @ K^T (3-term) ----
    const int mt = wid & 3;
    const int nh = wid >> 2;
    float Sacc[12][4];
    #pragma unroll
    for (int j = 0; j < 12; j++)
        #pragma unroll
        for (int r = 0; r < 4; r++) Sacc[j][r] = 0.0f;

    const uint32_t aOffBase = (mt * 16 + (lane & 15)) * 144;
    const uint32_t aHalf = (lane >> 4);
    const uint32_t bRowOff = (lane & 7) + ((lane >> 4) << 3);
    const uint32_t bHalf = (lane >> 3) & 1;

    #pragma unroll
    for (int kc = 0; kc < 4; kc++) {
        uint32_t ah[4], al[4];
        uint32_t aoff = aOffBase + (kc * 2 + aHalf) * 16;
        LDSM4(ah, sb + AQ_H + aoff);
        LDSM4(al, sb + AQ_L + aoff);
        #pragma unroll
        for (int jp = 0; jp < 6; jp++) {
            uint32_t bhf[4], blf[4];
            uint32_t boff = (nh * 96 + jp * 16 + bRowOff) * 144 + (kc * 2 + bHalf) * 16;
            LDSM4(bhf, sb + AK_H + boff);
            LDSM4(blf, sb + AK_L + boff);
            #pragma unroll
            for (int jj = 0; jj < 2; jj++) {
                int j = jp * 2 + jj, jo = jj * 2;
                MMA16816(Sacc[j], ah, (bhf + jo));
                MMA16816(Sacc[j], ah, (blf + jo));
                MMA16816(Sacc[j], al, (bhf + jo));
            }
        }
    }
    __syncthreads();

    {
        int r0 = mt * 16 + (lane >> 2);
        #pragma unroll
        for (int j = 0; j < 12; j++) {
            int cc = nh * 96 + j * 8 + (lane & 3) * 2;
            *(float2*)(sm + AS_OFF + r0 * 800 + cc * 4) = make_float2(Sacc[j][0], Sacc[j][1]);
            *(float2*)(sm + AS_OFF + (r0 + 8) * 800 + cc * 4) = make_float2(Sacc[j][2], Sacc[j][3]);
        }
    }
    __syncthreads();

    // ---- phase 2: softmax (row = tid/4, 4 threads per row x 48 cols) ----
    {
        int r = tid >> 2, tg = tid & 3;
        const float* Sp = (const float*)(sm + AS_OFF + r * 800);
        // allowed keys: s in [max(0, t-127), t]  ->  j in [max(r+1, -kbase), r+128]
        int jlo = r + 1;
        if (kbase < 0 && jlo < -kbase) jlo = -kbase;   // s >= 0 clamp (FIX)
        int jhi = r + 128;
        float mx = -1e30f;
        #pragma unroll 8
        for (int j2 = 0; j2 < 48; j2++) {
            int j = tg * 48 + j2;
            float v = Sp[j];
            bool ok = (j >= jlo) && (j <= jhi);
            mx = fmaxf(mx, ok ? v : -1e30f);
        }
        mx = fmaxf(mx, __shfl_xor_sync(0xffffffffu, mx, 1));
        mx = fmaxf(mx, __shfl_xor_sync(0xffffffffu, mx, 2));
        float sum = 0.0f;
        #pragma unroll 4
        for (int j2 = 0; j2 < 48; j2 += 2) {
            int j = tg * 48 + j2;
            float v0 = Sp[j], v1 = Sp[j + 1];
            bool ok0 = (j >= jlo) && (j <= jhi);
            bool ok1 = (j + 1 >= jlo) && (j + 1 <= jhi);
            float p0 = ok0 ? __expf(v0 - mx) : 0.0f;
            float p1 = ok1 ? __expf(v1 - mx) : 0.0f;
            sum += p0 + p1;
            split2(p0, p1, (bf16*)(sm + AP_H + r * 400 + j * 2),
                           (bf16*)(sm + AP_L + r * 400 + j * 2));
        }
        sum += __shfl_xor_sync(0xffffffffu, sum, 1);
        sum += __shfl_xor_sync(0xffffffffu, sum, 2);
        if (tg == 0) *(float*)(sm + ASUM + r * 4) = sum;
    }
    __syncthreads();

    // ---- phase 3: ctx = P @ V (3-term) ----
    const int dh = wid >> 2;
    float Cacc[4][4];
    #pragma unroll
    for (int j = 0; j < 4; j++)
        #pragma unroll
        for (int r = 0; r < 4; r++) Cacc[j][r] = 0.0f;

    const uint32_t pOffBase = (mt * 16 + (lane & 15)) * 400;
    #pragma unroll
    for (int kc = 0; kc < 12; kc++) {
        uint32_t pah[4], pal[4];
        uint32_t poff = pOffBase + (kc * 2 + aHalf) * 16;
        LDSM4(pah, sb + AP_H + poff);
        LDSM4(pal, sb + AP_L + poff);
        #pragma unroll
        for (int jp = 0; jp < 2; jp++) {
            uint32_t vbh[4], vbl[4];
            uint32_t voff = (dh * 32 + jp * 16 + bRowOff) * 400 + (kc * 2 + bHalf) * 16;
            LDSM4(vbh, sb + AV_H + voff);
            LDSM4(vbl, sb + AV_L + voff);
            #pragma unroll
            for (int jj = 0; jj < 2; jj++) {
                int j = jp * 2 + jj, jo = jj * 2;
                MMA16816(Cacc[j], pah, (vbh + jo));
                MMA16816(Cacc[j], pah, (vbl + jo));
                MMA16816(Cacc[j], pal, (vbh + jo));
            }
        }
    }

    {
        int b = bh >> 3, h = bh & 7;
        int rl0 = mt * 16 + (lane >> 2);
        float inv0 = 1.0f / *(const float*)(sm + ASUM + rl0 * 4);
        float inv1 = 1.0f / *(const float*)(sm + ASUM + (rl0 + 8) * 4);
        #pragma unroll
        for (int j = 0; j < 4; j++) {
            int d = dh * 32 + j * 8 + (lane & 3) * 2;
            size_t ob0 = ((size_t)(b * 2048 + t0 + rl0)) * 512 + h * 64 + d;
            size_t ob1 = ob0 + (size_t)8 * 512;
            split2(Cacc[j][0] * inv0, Cacc[j][1] * inv0, ctxh + ob0, ctxl + ob0);
            split2(Cacc[j][2] * inv1, Cacc[j][3] * inv1, ctxh + ob1, ctxl + ob1);
        }
    }
}

// ---------------- launch ----------------
extern "C" void kernel_launch(void* const* d_in, const int* in_sizes, int n_in,
                              void* d_out, int out_size) {
    const float* x     = (const float*)d_in[0];
    const float* in_w  = (const float*)d_in[1];
    const float* in_b  = (const float*)d_in[2];
    const float* out_w = (const float*)d_in[3];
    const float* out_b = (const float*)d_in[4];
    const float* ln1_g = (const float*)d_in[5];
    const float* ln1_b = (const float*)d_in[6];
    const float* ln2_g = (const float*)d_in[7];
    const float* ln2_b = (const float*)d_in[8];
    const float* w1    = (const float*)d_in[9];
    const float* b1    = (const float*)d_in[10];
    const float* w2    = (const float*)d_in[11];
    const float* b2    = (const float*)d_in[12];
    float* out = (float*)d_out;

    bf16 *pqh, *pql, *pkh, *pkl, *pvth, *pvtl;
    bf16 *px2h, *px2l, *pctxh, *pctxl, *px3h, *px3l, *phh, *phl;
    bf16 *pwah, *pwal, *pwbh, *pwbl, *pw1h, *pw1l, *pw2h, *pw2l;
    cudaGetSymbolAddress((void**)&pqh, g_qh);    cudaGetSymbolAddress((void**)&pql, g_ql);
    cudaGetSymbolAddress((void**)&pkh, g_kh);    cudaGetSymbolAddress((void**)&pkl, g_kl);
    cudaGetSymbolAddress((void**)&pvth, g_vth);  cudaGetSymbolAddress((void**)&pvtl, g_vtl);
    cudaGetSymbolAddress((void**)&px2h, g_x2h);  cudaGetSymbolAddress((void**)&px2l, g_x2l);
    cudaGetSymbolAddress((void**)&pctxh, g_ctxh); cudaGetSymbolAddress((void**)&pctxl, g_ctxl);
    cudaGetSymbolAddress((void**)&px3h, g_x3h);  cudaGetSymbolAddress((void**)&px3l, g_x3l);
    cudaGetSymbolAddress((void**)&phh, g_hh);    cudaGetSymbolAddress((void**)&phl, g_hl);
    cudaGetSymbolAddress((void**)&pwah, g_wah);  cudaGetSymbolAddress((void**)&pwal, g_wal);
    cudaGetSymbolAddress((void**)&pwbh, g_wbh);  cudaGetSymbolAddress((void**)&pwbl, g_wbl);
    cudaGetSymbolAddress((void**)&pw1h, g_w1h);  cudaGetSymbolAddress((void**)&pw1l, g_w1l);
    cudaGetSymbolAddress((void**)&pw2h, g_w2h);  cudaGetSymbolAddress((void**)&pw2l, g_w2l);

    cudaFuncSetAttribute(gemm_mma<EPI_BIAS>,       cudaFuncAttributeMaxDynamicSharedMemorySize, GEMM_SMEM);
    cudaFuncSetAttribute(gemm_mma<EPI_BIAS_RES>,   cudaFuncAttributeMaxDynamicSharedMemorySize, GEMM_SMEM);
    cudaFuncSetAttribute(gemm_mma<EPI_GELU_SPLIT>, cudaFuncAttributeMaxDynamicSharedMemorySize, GEMM_SMEM);
    cudaFuncSetAttribute(gemm_mma<EPI_QKV>,        cudaFuncAttributeMaxDynamicSharedMemorySize, GEMM_SMEM);
    cudaFuncSetAttribute(attn_mma, cudaFuncAttributeMaxDynamicSharedMemorySize, ATT_SMEM);

    // 0) split weights
    split_kernel<<<(1536 * 512 / 4 + 255) / 256, 256>>>(in_w,  pwah, pwal, 1536 * 512 / 4);
    split_kernel<<<(512 * 512 / 4 + 255) / 256, 256>>>(out_w, pwbh, pwbl, 512 * 512 / 4);
    split_kernel<<<(2048 * 512 / 4 + 255) / 256, 256>>>(w1,    pw1h, pw1l, 2048 * 512 / 4);
    split_kernel<<<(512 * 2048 / 4 + 255) / 256, 256>>>(w2,    pw2h, pw2l, 512 * 2048 / 4);

    // 1) x2 = LN1(x)
    ln_split_kernel<<<8192, 128>>>(x, ln1_g, ln1_b, px2h, px2l);

    // 2) qkv projection -> q,k (natural, q scaled), v (transposed), all bf16 hi/lo
    {
        dim3 grid(1536 / 128, 8192 / 128);
        gemm_mma<EPI_QKV><<<grid, 128, GEMM_SMEM>>>(px2h, px2l, pwah, pwal, in_b, nullptr,
                                                    nullptr, pqh, pql, pkh, pkl, pvth, pvtl,
                                                    1536, 512);
    }

    // 3) ctx = sliding-window attention (mma)
    {
        dim3 grid(2048 / 64, 32);
        attn_mma<<<grid, 256, ATT_SMEM>>>(pqh, pql, pkh, pkl, pvth, pvtl, pctxh, pctxl);
    }

    // 4) out = x + ctx @ out_w^T + out_b
    {
        dim3 grid(512 / 128, 8192 / 128);
        gemm_mma<EPI_BIAS_RES><<<grid, 128, GEMM_SMEM>>>(pctxh, pctxl, pwbh, pwbl, out_b, x,
                                                         out, nullptr, nullptr,
                                                         nullptr, nullptr, nullptr, nullptr,
                                                         512, 512);
    }

    // 5) x3 = LN2(out)
    ln_split_kernel<<<8192, 128>>>(out, ln2_g, ln2_b, px3h, px3l);

    // 6) h = gelu(x3 @ w1^T + b1)
    {
        dim3 grid(2048 / 128, 8192 / 128);
        gemm_mma<EPI_GELU_SPLIT><<<grid, 128, GEMM_SMEM>>>(px3h, px3l, pw1h, pw1l, b1, nullptr,
                                                           nullptr, phh, phl,
                                                           nullptr, nullptr, nullptr, nullptr,
                                                           2048, 512);
    }

    // 7) out = out + h @ w2^T + b2
    {
        dim3 grid(512 / 128, 8192 / 128);
        gemm_mma<EPI_BIAS_RES><<<grid, 128, GEMM_SMEM>>>(phh, phl, pw2h, pw2l, b2, out,
                                                         out, nullptr, nullptr,
                                                         nullptr, nullptr, nullptr, nullptr,
                                                         512, 2048);
    }
}

// round 8
// speedup vs baseline: 2.9298x; 1.1316x over previous
#include <cuda_runtime.h>
#include <cuda_bf16.h>
#include <math.h>
#include <stdint.h>

typedef __nv_bfloat16 bf16;

// B=4, T=2048, D=512, H=8, HD=64, F=2048, WINDOW=128, rows=8192

// ---------------- scratch ----------------
__device__ bf16  g_qh [32 * 2048 * 64], g_ql [32 * 2048 * 64];   // [bh][t][d], scaled
__device__ bf16  g_kh [32 * 2048 * 64], g_kl [32 * 2048 * 64];   // [bh][t][d]
__device__ bf16  g_vth[32 * 64 * 2048], g_vtl[32 * 64 * 2048];   // [bh][d][t]
__device__ bf16  g_x2h [8192 * 512],  g_x2l [8192 * 512];
__device__ bf16  g_ctxh[8192 * 512],  g_ctxl[8192 * 512];
__device__ bf16  g_x3h [8192 * 512],  g_x3l [8192 * 512];
__device__ bf16  g_hh  [8192 * 2048], g_hl  [8192 * 2048];
__device__ bf16  g_wah [1536 * 512],  g_wal [1536 * 512];
__device__ bf16  g_wbh [512 * 512],   g_wbl [512 * 512];
__device__ bf16  g_w1h [2048 * 512],  g_w1l [2048 * 512];
__device__ bf16  g_w2h [512 * 2048],  g_w2l [512 * 2048];

// ---------------- helpers ----------------
__device__ __forceinline__ uint32_t smem_u32(const void* p) {
    uint32_t a;
    asm("{ .reg .u64 t; cvta.to.shared.u64 t, %1; cvt.u32.u64 %0, t; }" : "=r"(a) : "l"(p));
    return a;
}
__device__ __forceinline__ void cp16(uint32_t d, const void* g) {
    asm volatile("cp.async.cg.shared.global [%0], [%1], 16;" :: "r"(d), "l"(g));
}
__device__ __forceinline__ void cp16z(uint32_t d, const void* g, uint32_t srcsz) {
    asm volatile("cp.async.cg.shared.global [%0], [%1], 16, %2;" :: "r"(d), "l"(g), "r"(srcsz));
}
#define CP_COMMIT() asm volatile("cp.async.commit_group;" ::: "memory")
#define CP_WAIT(n)  asm volatile("cp.async.wait_group %0;" :: "n"(n) : "memory")

#define LDSM4(r, addr) \
    asm volatile("ldmatrix.sync.aligned.m8n8.x4.shared.b16 {%0,%1,%2,%3}, [%4];" \
        : "=r"((r)[0]), "=r"((r)[1]), "=r"((r)[2]), "=r"((r)[3]) : "r"(addr))

#define MMA16816(c, a, b) \
    asm volatile("mma.sync.aligned.m16n8k16.row.col.f32.bf16.bf16.f32 " \
        "{%0,%1,%2,%3}, {%4,%5,%6,%7}, {%8,%9}, {%0,%1,%2,%3};" \
        : "+f"((c)[0]), "+f"((c)[1]), "+f"((c)[2]), "+f"((c)[3]) \
        : "r"((a)[0]), "r"((a)[1]), "r"((a)[2]), "r"((a)[3]), "r"((b)[0]), "r"((b)[1]))

__device__ __forceinline__ void split2(float a, float b, bf16* hp, bf16* lp) {
    bf16 h0 = __float2bfloat16_rn(a), h1 = __float2bfloat16_rn(b);
    bf16 l0 = __float2bfloat16_rn(a - __bfloat162float(h0));
    bf16 l1 = __float2bfloat16_rn(b - __bfloat162float(h1));
    __nv_bfloat162 hv = {h0, h1}, lv = {l0, l1};
    *(__nv_bfloat162*)hp = hv;
    *(__nv_bfloat162*)lp = lv;
}

// ---------------- fused weight split: all 4 weights in one launch ----------------
__global__ void split_all_kernel(const float* __restrict__ in_w, const float* __restrict__ out_w,
                                 const float* __restrict__ w1, const float* __restrict__ w2,
                                 bf16* __restrict__ wah, bf16* __restrict__ wal,
                                 bf16* __restrict__ wbh, bf16* __restrict__ wbl,
                                 bf16* __restrict__ w1h, bf16* __restrict__ w1l,
                                 bf16* __restrict__ w2h, bf16* __restrict__ w2l) {
    int i = blockIdx.x * 256 + threadIdx.x;   // unit = 4 floats; total 786432
    const float* src; bf16 *hi, *lo; int off;
    if (i < 196608)      { src = in_w;  hi = wah; lo = wal; off = i; }
    else if (i < 262144) { src = out_w; hi = wbh; lo = wbl; off = i - 196608; }
    else if (i < 524288) { src = w1;    hi = w1h; lo = w1l; off = i - 262144; }
    else                 { src = w2;    hi = w2h; lo = w2l; off = i - 524288; }
    float4 v = *(const float4*)(src + (size_t)off * 4);
    split2(v.x, v.y, hi + (size_t)off * 4,     lo + (size_t)off * 4);
    split2(v.z, v.w, hi + (size_t)off * 4 + 2, lo + (size_t)off * 4 + 2);
}

// ---------------- LayerNorm with split output ----------------
__global__ void ln_split_kernel(const float* __restrict__ x, const float* __restrict__ gw,
                                const float* __restrict__ bw, bf16* __restrict__ hi,
                                bf16* __restrict__ lo) {
    int row = blockIdx.x;
    int t = threadIdx.x;
    const float* xr = x + (size_t)row * 512;
    float4 v = *(const float4*)(xr + t * 4);
    float s  = v.x + v.y + v.z + v.w;
    float sq = v.x * v.x + v.y * v.y + v.z * v.z + v.w * v.w;
    #pragma unroll
    for (int o = 16; o > 0; o >>= 1) {
        s  += __shfl_xor_sync(0xffffffffu, s,  o);
        sq += __shfl_xor_sync(0xffffffffu, sq, o);
    }
    __shared__ float red[8];
    int wid = t >> 5, lane = t & 31;
    if (lane == 0) { red[wid] = s; red[4 + wid] = sq; }
    __syncthreads();
    float S  = red[0] + red[1] + red[2] + red[3];
    float SQ = red[4] + red[5] + red[6] + red[7];
    float mu   = S * (1.0f / 512.0f);
    float var  = SQ * (1.0f / 512.0f) - mu * mu;
    float rstd = rsqrtf(var + 1e-5f);
    float4 gv = *(const float4*)(gw + t * 4);
    float4 bv = *(const float4*)(bw + t * 4);
    float o0 = (v.x - mu) * rstd * gv.x + bv.x;
    float o1 = (v.y - mu) * rstd * gv.y + bv.y;
    float o2 = (v.z - mu) * rstd * gv.z + bv.z;
    float o3 = (v.w - mu) * rstd * gv.w + bv.w;
    size_t base = (size_t)row * 512 + t * 4;
    split2(o0, o1, hi + base, lo + base);
    split2(o2, o3, hi + base + 2, lo + base + 2);
}

// ---------------- mma.sync GEMM (3-term bf16 split) ----------------
// CTA 128x128, 4 warps of 64x64, BK=32, 3-stage cp.async, XOR-swizzled 64B rows.
// swizzle: chunk' = chunk ^ ((row>>1)&3)  -> conflict-free ldmatrix phases.
#define EPI_BIAS       0
#define EPI_BIAS_RES   1
#define EPI_GELU_SPLIT 2
#define EPI_QKV        3

#define TILE_B   8192            // 128 rows x 64 B
#define STAGE_B  (4 * TILE_B)    // 32768
#define NSTAGE   3
#define GEMM_SMEM (NSTAGE * STAGE_B)   // 98304

#define SWIZ(row, chunk) ((row) * 64 + (((chunk) ^ (((row) >> 1) & 3)) << 4))

template<int EPI>
__global__ __launch_bounds__(128)
void gemm_mma(const bf16* __restrict__ Ah, const bf16* __restrict__ Al,
              const bf16* __restrict__ Bh, const bf16* __restrict__ Bl,
              const float* __restrict__ bias, const float* __restrict__ res,
              float* __restrict__ Cf, bf16* __restrict__ Ch, bf16* __restrict__ Cl,
              bf16* __restrict__ Kh, bf16* __restrict__ Kl,
              bf16* __restrict__ Vth, bf16* __restrict__ Vtl,
              int N, int K) {
    extern __shared__ char sm[];
    const int tid = threadIdx.x;
    const int lane = tid & 31, wid = tid >> 5;
    const int wm = wid & 1, wn = wid >> 1;
    const int m0 = blockIdx.y * 128, n0 = blockIdx.x * 128;
    const uint32_t sbase = smem_u32(sm);

    const bf16* srcs[4] = { Ah + (size_t)m0 * K, Al + (size_t)m0 * K,
                            Bh + (size_t)n0 * K, Bl + (size_t)n0 * K };

    // one stage = 4 tiles of 128 rows x 32 bf16 (64B rows, XOR swizzle)
    auto load_stage = [&](int s, int kb) {
        uint32_t so = sbase + (uint32_t)s * STAGE_B;
        #pragma unroll
        for (int tt = 0; tt < 4; tt++) {
            const bf16* gp = srcs[tt] + kb * 32;
            uint32_t tb = so + tt * TILE_B;
            #pragma unroll
            for (int it = 0; it < 4; it++) {
                int idx = tid + it * 128;          // 0..511
                int r = idx >> 2, c = idx & 3;
                cp16(tb + SWIZ(r, c), gp + (size_t)r * K + c * 8);
            }
        }
    };

    float acc[4][8][4];
    #pragma unroll
    for (int i = 0; i < 4; i++)
        #pragma unroll
        for (int j = 0; j < 8; j++)
            #pragma unroll
            for (int r = 0; r < 4; r++) acc[i][j][r] = 0.0f;

    const int nkb = K >> 5;

    // prologue: stages 0,1
    load_stage(0, 0); CP_COMMIT();
    if (nkb > 1) load_stage(1, 1);
    CP_COMMIT();

    const uint32_t aRow = wm * 64 + (lane & 15);
    const uint32_t aChunkHalf = (lane >> 4);
    const uint32_t bRow = wn * 64 + (lane & 7) + ((lane >> 4) << 3);
    const uint32_t bChunkHalf = (lane >> 3) & 1;

    for (int kb = 0; kb < nkb; kb++) {
        bool more = (kb + NSTAGE - 1) < nkb;
        if (more) { CP_WAIT(NSTAGE - 2); } else { CP_WAIT(0); }
        __syncthreads();
        if (more) { load_stage((kb + NSTAGE - 1) % NSTAGE, kb + NSTAGE - 1); CP_COMMIT(); }

        uint32_t so = sbase + (uint32_t)(kb % NSTAGE) * STAGE_B;
        #pragma unroll
        for (int ks = 0; ks < 2; ks++) {
            const uint32_t kcA = ks * 2 + aChunkHalf;
            const uint32_t kcB = ks * 2 + bChunkHalf;
            uint32_t Ahf[4][4], Alf[4][4];
            #pragma unroll
            for (int i = 0; i < 4; i++) {
                uint32_t row = aRow + i * 16;
                uint32_t off = SWIZ(row, kcA);
                LDSM4(Ahf[i], so + off);
                LDSM4(Alf[i], so + TILE_B + off);
            }
            uint32_t Bhf[4][4], Blf[4][4];
            #pragma unroll
            for (int jp = 0; jp < 4; jp++) {
                uint32_t row = bRow + jp * 16;
                uint32_t off = SWIZ(row, kcB);
                LDSM4(Bhf[jp], so + 2 * TILE_B + off);
                LDSM4(Blf[jp], so + 3 * TILE_B + off);
            }
            #pragma unroll
            for (int i = 0; i < 4; i++) {
                #pragma unroll
                for (int j = 0; j < 8; j++) {
                    int jp = j >> 1, jo = (j & 1) * 2;
                    MMA16816(acc[i][j], Ahf[i], (Bhf[jp] + jo));
                    MMA16816(acc[i][j], Ahf[i], (Blf[jp] + jo));
                    MMA16816(acc[i][j], Alf[i], (Bhf[jp] + jo));
                }
            }
        }
    }

    // ---------------- epilogue ----------------
    #pragma unroll
    for (int i = 0; i < 4; i++) {
        int rb = m0 + wm * 64 + i * 16 + (lane >> 2);
        #pragma unroll
        for (int j = 0; j < 8; j++) {
            int col = n0 + wn * 64 + j * 8 + (lane & 3) * 2;
            float b0 = bias[col], b1 = bias[col + 1];
            #pragma unroll
            for (int half = 0; half < 2; half++) {
                int row = rb + half * 8;
                float o0 = acc[i][j][half * 2 + 0] + b0;
                float o1 = acc[i][j][half * 2 + 1] + b1;
                if (EPI == EPI_QKV) {
                    int b = row >> 11, t = row & 2047;
                    if (col < 512) {
                        int h = col >> 6, d = col & 63;
                        size_t ob = ((size_t)(b * 8 + h) * 2048 + t) * 64 + d;
                        split2(o0 * 0.125f, o1 * 0.125f, Ch + ob, Cl + ob);
                    } else if (col < 1024) {
                        int c = col - 512;
                        int h = c >> 6, d = c & 63;
                        size_t ob = ((size_t)(b * 8 + h) * 2048 + t) * 64 + d;
                        split2(o0, o1, Kh + ob, Kl + ob);
                    } else {
                        int c = col - 1024;
                        int h = c >> 6, d = c & 63;
                        size_t ob = ((size_t)(b * 8 + h) * 64 + d) * 2048 + t;
                        bf16 h0 = __float2bfloat16_rn(o0), h1 = __float2bfloat16_rn(o1);
                        Vth[ob] = h0;          Vth[ob + 2048] = h1;
                        Vtl[ob] = __float2bfloat16_rn(o0 - __bfloat162float(h0));
                        Vtl[ob + 2048] = __float2bfloat16_rn(o1 - __bfloat162float(h1));
                    }
                    continue;
                }
                size_t ob = (size_t)row * N + col;
                if (EPI == EPI_BIAS_RES) {
                    float2 rv = *(const float2*)(res + ob);
                    o0 += rv.x; o1 += rv.y;
                }
                if (EPI == EPI_GELU_SPLIT) {
                    o0 = 0.5f * o0 * (1.0f + erff(o0 * 0.70710678118654752f));
                    o1 = 0.5f * o1 * (1.0f + erff(o1 * 0.70710678118654752f));
                    split2(o0, o1, Ch + ob, Cl + ob);
                } else {
                    float2 o = make_float2(o0, o1);
                    *(float2*)(Cf + ob) = o;
                }
            }
        }
    }
}

// ---------------- mma attention (unchanged from R6) ----------------
#define AQ_H   0u
#define AQ_L   9216u
#define AK_H   18432u
#define AK_L   46080u
#define AV_H   73728u
#define AV_L   99328u
#define AP_H   124928u
#define AP_L   150528u
#define AS_OFF 18432u
#define ASUM   176128u
#define ATT_SMEM 176384u

__global__ __launch_bounds__(256)
void attn_mma(const bf16* __restrict__ qh, const bf16* __restrict__ ql,
              const bf16* __restrict__ kh, const bf16* __restrict__ kl,
              const bf16* __restrict__ vth, const bf16* __restrict__ vtl,
              bf16* __restrict__ ctxh, bf16* __restrict__ ctxl) {
    extern __shared__ char sm[];
    const uint32_t sb = smem_u32(sm);
    const int tid = threadIdx.x;
    const int lane = tid & 31, wid = tid >> 5;
    const int bh = blockIdx.y;
    const int t0 = blockIdx.x * 64;
    const int kbase = t0 - 128;

    {
        #pragma unroll
        for (int cpi = 0; cpi < 2; cpi++) {
            const bf16* src = cpi ? ql : qh;
            uint32_t dst = sb + (cpi ? AQ_L : AQ_H);
            #pragma unroll
            for (int it = 0; it < 2; it++) {
                int idx = tid + it * 256;
                int r = idx >> 3, c = idx & 7;
                cp16(dst + r * 144 + c * 16, src + ((size_t)bh * 2048 + t0 + r) * 64 + c * 8);
            }
        }
        #pragma unroll
        for (int cpi = 0; cpi < 2; cpi++) {
            const bf16* src = cpi ? kl : kh;
            uint32_t dst = sb + (cpi ? AK_L : AK_H);
            #pragma unroll
            for (int it = 0; it < 6; it++) {
                int idx = tid + it * 256;
                int r = idx >> 3, c = idx & 7;
                int s = kbase + r;
                uint32_t sz = (s >= 0) ? 16u : 0u;
                int sc = s < 0 ? 0 : s;
                cp16z(dst + r * 144 + c * 16, src + ((size_t)bh * 2048 + sc) * 64 + c * 8, sz);
            }
        }
        #pragma unroll
        for (int cpi = 0; cpi < 2; cpi++) {
            const bf16* src = cpi ? vtl : vth;
            uint32_t dst = sb + (cpi ? AV_L : AV_H);
            #pragma unroll
            for (int it = 0; it < 6; it++) {
                int idx = tid + it * 256;
                int r = idx / 24, c = idx - r * 24;
                int scol = kbase + c * 8;
                uint32_t sz = (scol >= 0) ? 16u : 0u;
                int sc = scol < 0 ? 0 : scol;
                cp16z(dst + r * 400 + c * 16, src + ((size_t)bh * 64 + r) * 2048 + sc, sz);
            }
        }
    }
    CP_COMMIT();
    CP_WAIT(0);
    __syncthreads();

    const int mt = wid & 3;
    const int nh = wid >> 2;
    float Sacc[12][4];
    #pragma unroll
    for (int j = 0; j < 12; j++)
        #pragma unroll
        for (int r = 0; r < 4; r++) Sacc[j][r] = 0.0f;

    const uint32_t aOffBase = (mt * 16 + (lane & 15)) * 144;
    const uint32_t aHalf = (lane >> 4);
    const uint32_t bRowOff = (lane & 7) + ((lane >> 4) << 3);
    const uint32_t bHalf = (lane >> 3) & 1;

    #pragma unroll
    for (int kc = 0; kc < 4; kc++) {
        uint32_t ah[4], al[4];
        uint32_t aoff = aOffBase + (kc * 2 + aHalf) * 16;
        LDSM4(ah, sb + AQ_H + aoff);
        LDSM4(al, sb + AQ_L + aoff);
        #pragma unroll
        for (int jp = 0; jp < 6; jp++) {
            uint32_t bhf[4], blf[4];
            uint32_t boff = (nh * 96 + jp * 16 + bRowOff) * 144 + (kc * 2 + bHalf) * 16;
            LDSM4(bhf, sb + AK_H + boff);
            LDSM4(blf, sb + AK_L + boff);
            #pragma unroll
            for (int jj = 0; jj < 2; jj++) {
                int j = jp * 2 + jj, jo = jj * 2;
                MMA16816(Sacc[j], ah, (bhf + jo));
                MMA16816(Sacc[j], ah, (blf + jo));
                MMA16816(Sacc[j], al, (bhf + jo));
            }
        }
    }
    __syncthreads();

    {
        int r0 = mt * 16 + (lane >> 2);
        #pragma unroll
        for (int j = 0; j < 12; j++) {
            int cc = nh * 96 + j * 8 + (lane & 3) * 2;
            *(float2*)(sm + AS_OFF + r0 * 800 + cc * 4) = make_float2(Sacc[j][0], Sacc[j][1]);
            *(float2*)(sm + AS_OFF + (r0 + 8) * 800 + cc * 4) = make_float2(Sacc[j][2], Sacc[j][3]);
        }
    }
    __syncthreads();

    {
        int r = tid >> 2, tg = tid & 3;
        const float* Sp = (const float*)(sm + AS_OFF + r * 800);
        int jlo = r + 1;
        if (kbase < 0 && jlo < -kbase) jlo = -kbase;
        int jhi = r + 128;
        float mx = -1e30f;
        #pragma unroll 8
        for (int j2 = 0; j2 < 48; j2++) {
            int j = tg * 48 + j2;
            float v = Sp[j];
            bool ok = (j >= jlo) && (j <= jhi);
            mx = fmaxf(mx, ok ? v : -1e30f);
        }
        mx = fmaxf(mx, __shfl_xor_sync(0xffffffffu, mx, 1));
        mx = fmaxf(mx, __shfl_xor_sync(0xffffffffu, mx, 2));
        float sum = 0.0f;
        #pragma unroll 4
        for (int j2 = 0; j2 < 48; j2 += 2) {
            int j = tg * 48 + j2;
            float v0 = Sp[j], v1 = Sp[j + 1];
            bool ok0 = (j >= jlo) && (j <= jhi);
            bool ok1 = (j + 1 >= jlo) && (j + 1 <= jhi);
            float p0 = ok0 ? __expf(v0 - mx) : 0.0f;
            float p1 = ok1 ? __expf(v1 - mx) : 0.0f;
            sum += p0 + p1;
            split2(p0, p1, (bf16*)(sm + AP_H + r * 400 + j * 2),
                           (bf16*)(sm + AP_L + r * 400 + j * 2));
        }
        sum += __shfl_xor_sync(0xffffffffu, sum, 1);
        sum += __shfl_xor_sync(0xffffffffu, sum, 2);
        if (tg == 0) *(float*)(sm + ASUM + r * 4) = sum;
    }
    __syncthreads();

    const int dh = wid >> 2;
    float Cacc[4][4];
    #pragma unroll
    for (int j = 0; j < 4; j++)
        #pragma unroll
        for (int r = 0; r < 4; r++) Cacc[j][r] = 0.0f;

    const uint32_t pOffBase = (mt * 16 + (lane & 15)) * 400;
    #pragma unroll
    for (int kc = 0; kc < 12; kc++) {
        uint32_t pah[4], pal[4];
        uint32_t poff = pOffBase + (kc * 2 + aHalf) * 16;
        LDSM4(pah, sb + AP_H + poff);
        LDSM4(pal, sb + AP_L + poff);
        #pragma unroll
        for (int jp = 0; jp < 2; jp++) {
            uint32_t vbh[4], vbl[4];
            uint32_t voff = (dh * 32 + jp * 16 + bRowOff) * 400 + (kc * 2 + bHalf) * 16;
            LDSM4(vbh, sb + AV_H + voff);
            LDSM4(vbl, sb + AV_L + voff);
            #pragma unroll
            for (int jj = 0; jj < 2; jj++) {
                int j = jp * 2 + jj, jo = jj * 2;
                MMA16816(Cacc[j], pah, (vbh + jo));
                MMA16816(Cacc[j], pah, (vbl + jo));
                MMA16816(Cacc[j], pal, (vbh + jo));
            }
        }
    }

    {
        int b = bh >> 3, h = bh & 7;
        int rl0 = mt * 16 + (lane >> 2);
        float inv0 = 1.0f / *(const float*)(sm + ASUM + rl0 * 4);
        float inv1 = 1.0f / *(const float*)(sm + ASUM + (rl0 + 8) * 4);
        #pragma unroll
        for (int j = 0; j < 4; j++) {
            int d = dh * 32 + j * 8 + (lane & 3) * 2;
            size_t ob0 = ((size_t)(b * 2048 + t0 + rl0)) * 512 + h * 64 + d;
            size_t ob1 = ob0 + (size_t)8 * 512;
            split2(Cacc[j][0] * inv0, Cacc[j][1] * inv0, ctxh + ob0, ctxl + ob0);
            split2(Cacc[j][2] * inv1, Cacc[j][3] * inv1, ctxh + ob1, ctxl + ob1);
        }
    }
}

// ---------------- launch ----------------
extern "C" void kernel_launch(void* const* d_in, const int* in_sizes, int n_in,
                              void* d_out, int out_size) {
    const float* x     = (const float*)d_in[0];
    const float* in_w  = (const float*)d_in[1];
    const float* in_b  = (const float*)d_in[2];
    const float* out_w = (const float*)d_in[3];
    const float* out_b = (const float*)d_in[4];
    const float* ln1_g = (const float*)d_in[5];
    const float* ln1_b = (const float*)d_in[6];
    const float* ln2_g = (const float*)d_in[7];
    const float* ln2_b = (const float*)d_in[8];
    const float* w1    = (const float*)d_in[9];
    const float* b1    = (const float*)d_in[10];
    const float* w2    = (const float*)d_in[11];
    const float* b2    = (const float*)d_in[12];
    float* out = (float*)d_out;

    bf16 *pqh, *pql, *pkh, *pkl, *pvth, *pvtl;
    bf16 *px2h, *px2l, *pctxh, *pctxl, *px3h, *px3l, *phh, *phl;
    bf16 *pwah, *pwal, *pwbh, *pwbl, *pw1h, *pw1l, *pw2h, *pw2l;
    cudaGetSymbolAddress((void**)&pqh, g_qh);    cudaGetSymbolAddress((void**)&pql, g_ql);
    cudaGetSymbolAddress((void**)&pkh, g_kh);    cudaGetSymbolAddress((void**)&pkl, g_kl);
    cudaGetSymbolAddress((void**)&pvth, g_vth);  cudaGetSymbolAddress((void**)&pvtl, g_vtl);
    cudaGetSymbolAddress((void**)&px2h, g_x2h);  cudaGetSymbolAddress((void**)&px2l, g_x2l);
    cudaGetSymbolAddress((void**)&pctxh, g_ctxh); cudaGetSymbolAddress((void**)&pctxl, g_ctxl);
    cudaGetSymbolAddress((void**)&px3h, g_x3h);  cudaGetSymbolAddress((void**)&px3l, g_x3l);
    cudaGetSymbolAddress((void**)&phh, g_hh);    cudaGetSymbolAddress((void**)&phl, g_hl);
    cudaGetSymbolAddress((void**)&pwah, g_wah);  cudaGetSymbolAddress((void**)&pwal, g_wal);
    cudaGetSymbolAddress((void**)&pwbh, g_wbh);  cudaGetSymbolAddress((void**)&pwbl, g_wbl);
    cudaGetSymbolAddress((void**)&pw1h, g_w1h);  cudaGetSymbolAddress((void**)&pw1l, g_w1l);
    cudaGetSymbolAddress((void**)&pw2h, g_w2h);  cudaGetSymbolAddress((void**)&pw2l, g_w2l);

    cudaFuncSetAttribute(gemm_mma<EPI_BIAS>,       cudaFuncAttributeMaxDynamicSharedMemorySize, GEMM_SMEM);
    cudaFuncSetAttribute(gemm_mma<EPI_BIAS_RES>,   cudaFuncAttributeMaxDynamicSharedMemorySize, GEMM_SMEM);
    cudaFuncSetAttribute(gemm_mma<EPI_GELU_SPLIT>, cudaFuncAttributeMaxDynamicSharedMemorySize, GEMM_SMEM);
    cudaFuncSetAttribute(gemm_mma<EPI_QKV>,        cudaFuncAttributeMaxDynamicSharedMemorySize, GEMM_SMEM);
    cudaFuncSetAttribute(attn_mma, cudaFuncAttributeMaxDynamicSharedMemorySize, ATT_SMEM);

    // 0) split all weights (one launch)
    split_all_kernel<<<3072, 256>>>(in_w, out_w, w1, w2,
                                    pwah, pwal, pwbh, pwbl, pw1h, pw1l, pw2h, pw2l);

    // 1) x2 = LN1(x)
    ln_split_kernel<<<8192, 128>>>(x, ln1_g, ln1_b, px2h, px2l);

    // 2) qkv projection -> q,k (natural, q scaled), v (transposed), all bf16 hi/lo
    {
        dim3 grid(1536 / 128, 8192 / 128);
        gemm_mma<EPI_QKV><<<grid, 128, GEMM_SMEM>>>(px2h, px2l, pwah, pwal, in_b, nullptr,
                                                    nullptr, pqh, pql, pkh, pkl, pvth, pvtl,
                                                    1536, 512);
    }

    // 3) ctx = sliding-window attention (mma)
    {
        dim3 grid(2048 / 64, 32);
        attn_mma<<<grid, 256, ATT_SMEM>>>(pqh, pql, pkh, pkl, pvth, pvtl, pctxh, pctxl);
    }

    // 4) out = x + ctx @ out_w^T + out_b
    {
        dim3 grid(512 / 128, 8192 / 128);
        gemm_mma<EPI_BIAS_RES><<<grid, 128, GEMM_SMEM>>>(pctxh, pctxl, pwbh, pwbl, out_b, x,
                                                         out, nullptr, nullptr,
                                                         nullptr, nullptr, nullptr, nullptr,
                                                         512, 512);
    }

    // 5) x3 = LN2(out)
    ln_split_kernel<<<8192, 128>>>(out, ln2_g, ln2_b, px3h, px3l);

    // 6) h = gelu(x3 @ w1^T + b1)
    {
        dim3 grid(2048 / 128, 8192 / 128);
        gemm_mma<EPI_GELU_SPLIT><<<grid, 128, GEMM_SMEM>>>(px3h, px3l, pw1h, pw1l, b1, nullptr,
                                                           nullptr, phh, phl,
                                                           nullptr, nullptr, nullptr, nullptr,
                                                           2048, 512);
    }

    // 7) out = out + h @ w2^T + b2
    {
        dim3 grid(512 / 128, 8192 / 128);
        gemm_mma<EPI_BIAS_RES><<<grid, 128, GEMM_SMEM>>>(phh, phl, pw2h, pw2l, b2, out,
                                                         out, nullptr, nullptr,
                                                         nullptr, nullptr, nullptr, nullptr,
                                                         512, 2048);
    }
}

// round 10
// speedup vs baseline: 3.9366x; 1.3436x over previous
#include <cuda_runtime.h>
#include <cuda_fp16.h>
#include <math.h>
#include <stdint.h>

typedef __half h16;

// B=4, T=2048, D=512, H=8, HD=64, F=2048, WINDOW=128, rows=8192

// ---------------- scratch ----------------
__device__ h16  g_qh [32 * 2048 * 64], g_ql [32 * 2048 * 64];   // [bh][t][d], scaled, hi/lo
__device__ h16  g_k  [32 * 2048 * 64];                          // [bh][t][d] single
__device__ h16  g_vt [32 * 64 * 2048];                          // [bh][d][t] single
__device__ h16  g_x2h [8192 * 512],  g_x2l [8192 * 512];
__device__ h16  g_ctxh[8192 * 512],  g_ctxl[8192 * 512];
__device__ h16  g_x3h [8192 * 512],  g_x3l [8192 * 512];
__device__ h16  g_hh  [8192 * 2048], g_hl  [8192 * 2048];
__device__ h16  g_wa [1536 * 512];   // weights: single fp16
__device__ h16  g_wb [512 * 512];
__device__ h16  g_w1 [2048 * 512];
__device__ h16  g_w2 [512 * 2048];

// ---------------- helpers ----------------
__device__ __forceinline__ uint32_t smem_u32(const void* p) {
    uint32_t a;
    asm("{ .reg .u64 t; cvta.to.shared.u64 t, %1; cvt.u32.u64 %0, t; }" : "=r"(a) : "l"(p));
    return a;
}
__device__ __forceinline__ void cp16(uint32_t d, const void* g) {
    asm volatile("cp.async.cg.shared.global [%0], [%1], 16;" :: "r"(d), "l"(g));
}
__device__ __forceinline__ void cp16z(uint32_t d, const void* g, uint32_t srcsz) {
    asm volatile("cp.async.cg.shared.global [%0], [%1], 16, %2;" :: "r"(d), "l"(g), "r"(srcsz));
}
#define CP_COMMIT() asm volatile("cp.async.commit_group;" ::: "memory")
#define CP_WAIT(n)  asm volatile("cp.async.wait_group %0;" :: "n"(n) : "memory")

#define LDSM4(r, addr) \
    asm volatile("ldmatrix.sync.aligned.m8n8.x4.shared.b16 {%0,%1,%2,%3}, [%4];" \
        : "=r"((r)[0]), "=r"((r)[1]), "=r"((r)[2]), "=r"((r)[3]) : "r"(addr))

#define MMA16816(c, a, b) \
    asm volatile("mma.sync.aligned.m16n8k16.row.col.f32.f16.f16.f32 " \
        "{%0,%1,%2,%3}, {%4,%5,%6,%7}, {%8,%9}, {%0,%1,%2,%3};" \
        : "+f"((c)[0]), "+f"((c)[1]), "+f"((c)[2]), "+f"((c)[3]) \
        : "r"((a)[0]), "r"((a)[1]), "r"((a)[2]), "r"((a)[3]), "r"((b)[0]), "r"((b)[1]))

__device__ __forceinline__ void splitH(float a, float b, h16* hp, h16* lp) {
    h16 h0 = __float2half_rn(a), h1 = __float2half_rn(b);
    h16 l0 = __float2half_rn(a - __half2float(h0));
    h16 l1 = __float2half_rn(b - __half2float(h1));
    *(__half2*)hp = __halves2half2(h0, h1);
    *(__half2*)lp = __halves2half2(l0, l1);
}
__device__ __forceinline__ void cvtH2(float a, float b, h16* p) {
    *(__half2*)p = __halves2half2(__float2half_rn(a), __float2half_rn(b));
}

// ---------------- fused weight convert: all 4 weights -> single fp16 ----------------
__global__ void split_all_kernel(const float* __restrict__ in_w, const float* __restrict__ out_w,
                                 const float* __restrict__ w1, const float* __restrict__ w2,
                                 h16* __restrict__ wa, h16* __restrict__ wb,
                                 h16* __restrict__ w1o, h16* __restrict__ w2o) {
    int i = blockIdx.x * 256 + threadIdx.x;   // unit = 4 floats; total 786432
    const float* src; h16* dst; int off;
    if (i < 196608)      { src = in_w;  dst = wa;  off = i; }
    else if (i < 262144) { src = out_w; dst = wb;  off = i - 196608; }
    else if (i < 524288) { src = w1;    dst = w1o; off = i - 262144; }
    else                 { src = w2;    dst = w2o; off = i - 524288; }
    float4 v = *(const float4*)(src + (size_t)off * 4);
    cvtH2(v.x, v.y, dst + (size_t)off * 4);
    cvtH2(v.z, v.w, dst + (size_t)off * 4 + 2);
}

// ---------------- LayerNorm with fp16 hi/lo output ----------------
__global__ void ln_split_kernel(const float* __restrict__ x, const float* __restrict__ gw,
                                const float* __restrict__ bw, h16* __restrict__ hi,
                                h16* __restrict__ lo) {
    int row = blockIdx.x;
    int t = threadIdx.x;
    const float* xr = x + (size_t)row * 512;
    float4 v = *(const float4*)(xr + t * 4);
    float s  = v.x + v.y + v.z + v.w;
    float sq = v.x * v.x + v.y * v.y + v.z * v.z + v.w * v.w;
    #pragma unroll
    for (int o = 16; o > 0; o >>= 1) {
        s  += __shfl_xor_sync(0xffffffffu, s,  o);
        sq += __shfl_xor_sync(0xffffffffu, sq, o);
    }
    __shared__ float red[8];
    int wid = t >> 5, lane = t & 31;
    if (lane == 0) { red[wid] = s; red[4 + wid] = sq; }
    __syncthreads();
    float S  = red[0] + red[1] + red[2] + red[3];
    float SQ = red[4] + red[5] + red[6] + red[7];
    float mu   = S * (1.0f / 512.0f);
    float var  = SQ * (1.0f / 512.0f) - mu * mu;
    float rstd = rsqrtf(var + 1e-5f);
    float4 gv = *(const float4*)(gw + t * 4);
    float4 bv = *(const float4*)(bw + t * 4);
    float o0 = (v.x - mu) * rstd * gv.x + bv.x;
    float o1 = (v.y - mu) * rstd * gv.y + bv.y;
    float o2 = (v.z - mu) * rstd * gv.z + bv.z;
    float o3 = (v.w - mu) * rstd * gv.w + bv.w;
    size_t base = (size_t)row * 512 + t * 4;
    splitH(o0, o1, hi + base, lo + base);
    splitH(o2, o3, hi + base + 2, lo + base + 2);
}

// ---------------- mma.sync GEMM: C = A @ W^T, A = Ah+Al (fp16 exact), W single fp16 ----------------
// CTA 128x128, 4 warps of 64x64, BK=32, 4-stage cp.async, XOR-swizzled 64B rows. 2 MMA terms.
#define EPI_BIAS_RES   1
#define EPI_GELU_SPLIT 2
#define EPI_QKV        3

#define TILE_B   8192            // 128 rows x 64 B
#define STAGE_B  (3 * TILE_B)    // 24576 (Ah, Al, W)
#define NSTAGE   4
#define GEMM_SMEM (NSTAGE * STAGE_B)   // 98304

#define SWIZ(row, chunk) ((row) * 64 + (((chunk) ^ (((row) >> 1) & 3)) << 4))

template<int EPI>
__global__ __launch_bounds__(128)
void gemm_mma(const h16* __restrict__ Ah, const h16* __restrict__ Al,
              const h16* __restrict__ W,
              const float* __restrict__ bias, const float* __restrict__ res,
              float* __restrict__ Cf, h16* __restrict__ Ch, h16* __restrict__ Cl,
              h16* __restrict__ Kh, h16* __restrict__ Vth,
              int N, int K) {
    extern __shared__ char sm[];
    const int tid = threadIdx.x;
    const int lane = tid & 31, wid = tid >> 5;
    const int wm = wid & 1, wn = wid >> 1;
    const int m0 = blockIdx.y * 128, n0 = blockIdx.x * 128;
    const uint32_t sbase = smem_u32(sm);

    const h16* srcs[3] = { Ah + (size_t)m0 * K, Al + (size_t)m0 * K, W + (size_t)n0 * K };

    auto load_stage = [&](int s, int kb) {
        uint32_t so = sbase + (uint32_t)s * STAGE_B;
        #pragma unroll
        for (int tt = 0; tt < 3; tt++) {
            const h16* gp = srcs[tt] + kb * 32;
            uint32_t tb = so + tt * TILE_B;
            #pragma unroll
            for (int it = 0; it < 4; it++) {
                int idx = tid + it * 128;          // 0..511
                int r = idx >> 2, c = idx & 3;
                cp16(tb + SWIZ(r, c), gp + (size_t)r * K + c * 8);
            }
        }
    };

    float acc[4][8][4];
    #pragma unroll
    for (int i = 0; i < 4; i++)
        #pragma unroll
        for (int j = 0; j < 8; j++)
            #pragma unroll
            for (int r = 0; r < 4; r++) acc[i][j][r] = 0.0f;

    const int nkb = K >> 5;

    // prologue: stages 0,1,2
    load_stage(0, 0); CP_COMMIT();
    load_stage(1, 1); CP_COMMIT();
    load_stage(2, 2); CP_COMMIT();

    const uint32_t aRow = wm * 64 + (lane & 15);
    const uint32_t aChunkHalf = (lane >> 4);
    const uint32_t bRow = wn * 64 + (lane & 7) + ((lane >> 4) << 3);
    const uint32_t bChunkHalf = (lane >> 3) & 1;

    for (int kb = 0; kb < nkb; kb++) {
        bool more = (kb + NSTAGE - 1) < nkb;
        if (more) { CP_WAIT(NSTAGE - 2); } else { CP_WAIT(0); }
        __syncthreads();
        if (more) { load_stage((kb + NSTAGE - 1) % NSTAGE, kb + NSTAGE - 1); CP_COMMIT(); }

        uint32_t so = sbase + (uint32_t)(kb % NSTAGE) * STAGE_B;
        #pragma unroll
        for (int ks = 0; ks < 2; ks++) {
            const uint32_t kcA = ks * 2 + aChunkHalf;
            const uint32_t kcB = ks * 2 + bChunkHalf;
            uint32_t Ahf[4][4], Alf[4][4];
            #pragma unroll
            for (int i = 0; i < 4; i++) {
                uint32_t off = SWIZ(aRow + i * 16, kcA);
                LDSM4(Ahf[i], so + off);
                LDSM4(Alf[i], so + TILE_B + off);
            }
            uint32_t Wf[4][4];
            #pragma unroll
            for (int jp = 0; jp < 4; jp++) {
                uint32_t off = SWIZ(bRow + jp * 16, kcB);
                LDSM4(Wf[jp], so + 2 * TILE_B + off);
            }
            #pragma unroll
            for (int i = 0; i < 4; i++) {
                #pragma unroll
                for (int j = 0; j < 8; j++) {
                    int jp = j >> 1, jo = (j & 1) * 2;
                    MMA16816(acc[i][j], Ahf[i], (Wf[jp] + jo));
                    MMA16816(acc[i][j], Alf[i], (Wf[jp] + jo));
                }
            }
        }
    }

    // ---------------- epilogue ----------------
    #pragma unroll
    for (int i = 0; i < 4; i++) {
        int rb = m0 + wm * 64 + i * 16 + (lane >> 2);
        #pragma unroll
        for (int j = 0; j < 8; j++) {
            int col = n0 + wn * 64 + j * 8 + (lane & 3) * 2;
            float b0 = bias[col], b1 = bias[col + 1];
            #pragma unroll
            for (int half = 0; half < 2; half++) {
                int row = rb + half * 8;
                float o0 = acc[i][j][half * 2 + 0] + b0;
                float o1 = acc[i][j][half * 2 + 1] + b1;
                if (EPI == EPI_QKV) {
                    int b = row >> 11, t = row & 2047;
                    if (col < 512) {
                        int h = col >> 6, d = col & 63;
                        size_t ob = ((size_t)(b * 8 + h) * 2048 + t) * 64 + d;
                        splitH(o0 * 0.125f, o1 * 0.125f, Ch + ob, Cl + ob);
                    } else if (col < 1024) {
                        int c = col - 512;
                        int h = c >> 6, d = c & 63;
                        size_t ob = ((size_t)(b * 8 + h) * 2048 + t) * 64 + d;
                        cvtH2(o0, o1, Kh + ob);
                    } else {
                        int c = col - 1024;
                        int h = c >> 6, d = c & 63;
                        size_t ob = ((size_t)(b * 8 + h) * 64 + d) * 2048 + t;
                        Vth[ob]        = __float2half_rn(o0);
                        Vth[ob + 2048] = __float2half_rn(o1);
                    }
                    continue;
                }
                size_t ob = (size_t)row * N + col;
                if (EPI == EPI_BIAS_RES) {
                    float2 rv = *(const float2*)(res + ob);
                    o0 += rv.x; o1 += rv.y;
                    float2 o = make_float2(o0, o1);
                    *(float2*)(Cf + ob) = o;
                }
                if (EPI == EPI_GELU_SPLIT) {
                    o0 = 0.5f * o0 * (1.0f + erff(o0 * 0.70710678118654752f));
                    o1 = 0.5f * o1 * (1.0f + erff(o1 * 0.70710678118654752f));
                    splitH(o0, o1, Ch + ob, Cl + ob);
                }
            }
        }
    }
}

// ---------------- mma attention (fp16; Q hi/lo, K/V/P/S single) ----------------
// block = (qtile 64, bh). keys = 192. 256 threads / 8 warps. smem 97.5KB -> 2 CTAs/SM.
#define AQ_H   0u          // Q hi: 64 x 144
#define AQ_L   9216u       // Q lo
#define AK     18432u      // K: 192 x 144
#define AV     46080u      // VT: 64 x 400
#define AP     71680u      // P fp16: 64 x 400
#define AS     0u          // S fp16 overlay (64 x 400 = 25600 over dead Q+K)
#define ASUM   97280u
#define ATT_SMEM 97536u

__global__ __launch_bounds__(256)
void attn_mma(const h16* __restrict__ qh, const h16* __restrict__ ql,
              const h16* __restrict__ kk, const h16* __restrict__ vt,
              h16* __restrict__ ctxh, h16* __restrict__ ctxl) {
    extern __shared__ char sm[];
    const uint32_t sb = smem_u32(sm);
    const int tid = threadIdx.x;
    const int lane = tid & 31, wid = tid >> 5;
    const int bh = blockIdx.y;
    const int t0 = blockIdx.x * 64;
    const int kbase = t0 - 128;

    // ---- loads ----
    {
        #pragma unroll
        for (int cpi = 0; cpi < 2; cpi++) {
            const h16* src = cpi ? ql : qh;
            uint32_t dst = sb + (cpi ? AQ_L : AQ_H);
            #pragma unroll
            for (int it = 0; it < 2; it++) {
                int idx = tid + it * 256;
                int r = idx >> 3, c = idx & 7;
                cp16(dst + r * 144 + c * 16, src + ((size_t)bh * 2048 + t0 + r) * 64 + c * 8);
            }
        }
        #pragma unroll
        for (int it = 0; it < 6; it++) {
            int idx = tid + it * 256;
            int r = idx >> 3, c = idx & 7;
            int s = kbase + r;
            uint32_t sz = (s >= 0) ? 16u : 0u;
            int sc = s < 0 ? 0 : s;
            cp16z(sb + AK + r * 144 + c * 16, kk + ((size_t)bh * 2048 + sc) * 64 + c * 8, sz);
        }
        #pragma unroll
        for (int it = 0; it < 6; it++) {
            int idx = tid + it * 256;
            int r = idx / 24, c = idx - r * 24;
            int scol = kbase + c * 8;
            uint32_t sz = (scol >= 0) ? 16u : 0u;
            int sc = scol < 0 ? 0 : scol;
            cp16z(sb + AV + r * 400 + c * 16, vt + ((size_t)bh * 64 + r) * 2048 + sc, sz);
        }
    }
    CP_COMMIT();
    CP_WAIT(0);
    __syncthreads();

    // ---- phase 1: S = Q @ K^T (2-term: (Qh+Ql)·K) ----
    const int mt = wid & 3;
    const int nh = wid >> 2;
    float Sacc[12][4];
    #pragma unroll
    for (int j = 0; j < 12; j++)
        #pragma unroll
        for (int r = 0; r < 4; r++) Sacc[j][r] = 0.0f;

    const uint32_t aOffBase = (mt * 16 + (lane & 15)) * 144;
    const uint32_t aHalf = (lane >> 4);
    const uint32_t bRowOff = (lane & 7) + ((lane >> 4) << 3);
    const uint32_t bHalf = (lane >> 3) & 1;

    #pragma unroll
    for (int kc = 0; kc < 4; kc++) {
        uint32_t ah[4], al[4];
        uint32_t aoff = aOffBase + (kc * 2 + aHalf) * 16;
        LDSM4(ah, sb + AQ_H + aoff);
        LDSM4(al, sb + AQ_L + aoff);
        #pragma unroll
        for (int jp = 0; jp < 6; jp++) {
            uint32_t bf[4];
            uint32_t boff = (nh * 96 + jp * 16 + bRowOff) * 144 + (kc * 2 + bHalf) * 16;
            LDSM4(bf, sb + AK + boff);
            #pragma unroll
            for (int jj = 0; jj < 2; jj++) {
                int j = jp * 2 + jj, jo = jj * 2;
                MMA16816(Sacc[j], ah, (bf + jo));
                MMA16816(Sacc[j], al, (bf + jo));
            }
        }
    }
    __syncthreads();   // Q and K reads done -> S may overlay them

    // write S (fp16)
    {
        int r0 = mt * 16 + (lane >> 2);
        #pragma unroll
        for (int j = 0; j < 12; j++) {
            int cc = nh * 96 + j * 8 + (lane & 3) * 2;
            cvtH2(Sacc[j][0], Sacc[j][1], (h16*)(sm + AS + r0 * 400 + cc * 2));
            cvtH2(Sacc[j][2], Sacc[j][3], (h16*)(sm + AS + (r0 + 8) * 400 + cc * 2));
        }
    }
    __syncthreads();

    // ---- phase 2: softmax (row = tid/4, 4 threads x 48 cols) ----
    {
        int r = tid >> 2, tg = tid & 3;
        const h16* Sp = (const h16*)(sm + AS + r * 400);
        int jlo = r + 1;
        if (kbase < 0 && jlo < -kbase) jlo = -kbase;
        int jhi = r + 128;
        float mx = -1e30f;
        #pragma unroll 8
        for (int j2 = 0; j2 < 48; j2++) {
            int j = tg * 48 + j2;
            float v = __half2float(Sp[j]);
            bool ok = (j >= jlo) && (j <= jhi);
            mx = fmaxf(mx, ok ? v : -1e30f);
        }
        mx = fmaxf(mx, __shfl_xor_sync(0xffffffffu, mx, 1));
        mx = fmaxf(mx, __shfl_xor_sync(0xffffffffu, mx, 2));
        float sum = 0.0f;
        #pragma unroll 4
        for (int j2 = 0; j2 < 48; j2 += 2) {
            int j = tg * 48 + j2;
            float v0 = __half2float(Sp[j]), v1 = __half2float(Sp[j + 1]);
            bool ok0 = (j >= jlo) && (j <= jhi);
            bool ok1 = (j + 1 >= jlo) && (j + 1 <= jhi);
            float p0 = ok0 ? __expf(v0 - mx) : 0.0f;
            float p1 = ok1 ? __expf(v1 - mx) : 0.0f;
            sum += p0 + p1;
            cvtH2(p0, p1, (h16*)(sm + AP + r * 400 + j * 2));
        }
        sum += __shfl_xor_sync(0xffffffffu, sum, 1);
        sum += __shfl_xor_sync(0xffffffffu, sum, 2);
        if (tg == 0) *(float*)(sm + ASUM + r * 4) = sum;
    }
    __syncthreads();

    // ---- phase 3: ctx = P @ V (1-term) ----
    const int dh = wid >> 2;
    float Cacc[4][4];
    #pragma unroll
    for (int j = 0; j < 4; j++)
        #pragma unroll
        for (int r = 0; r < 4; r++) Cacc[j][r] = 0.0f;

    const uint32_t pOffBase = (mt * 16 + (lane & 15)) * 400;
    #pragma unroll
    for (int kc = 0; kc < 12; kc++) {
        uint32_t pa[4];
        LDSM4(pa, sb + AP + pOffBase + (kc * 2 + aHalf) * 16);
        #pragma unroll
        for (int jp = 0; jp < 2; jp++) {
            uint32_t vb[4];
            uint32_t voff = (dh * 32 + jp * 16 + bRowOff) * 400 + (kc * 2 + bHalf) * 16;
            LDSM4(vb, sb + AV + voff);
            #pragma unroll
            for (int jj = 0; jj < 2; jj++) {
                int j = jp * 2 + jj, jo = jj * 2;
                MMA16816(Cacc[j], pa, (vb + jo));
            }
        }
    }

    // epilogue
    {
        int b = bh >> 3, h = bh & 7;
        int rl0 = mt * 16 + (lane >> 2);
        float inv0 = 1.0f / *(const float*)(sm + ASUM + rl0 * 4);
        float inv1 = 1.0f / *(const float*)(sm + ASUM + (rl0 + 8) * 4);
        #pragma unroll
        for (int j = 0; j < 4; j++) {
            int d = dh * 32 + j * 8 + (lane & 3) * 2;
            size_t ob0 = ((size_t)(b * 2048 + t0 + rl0)) * 512 + h * 64 + d;
            size_t ob1 = ob0 + (size_t)8 * 512;
            splitH(Cacc[j][0] * inv0, Cacc[j][1] * inv0, ctxh + ob0, ctxl + ob0);
            splitH(Cacc[j][2] * inv1, Cacc[j][3] * inv1, ctxh + ob1, ctxl + ob1);
        }
    }
}

// ---------------- launch ----------------
extern "C" void kernel_launch(void* const* d_in, const int* in_sizes, int n_in,
                              void* d_out, int out_size) {
    const float* x     = (const float*)d_in[0];
    const float* in_w  = (const float*)d_in[1];
    const float* in_b  = (const float*)d_in[2];
    const float* out_w = (const float*)d_in[3];
    const float* out_b = (const float*)d_in[4];
    const float* ln1_g = (const float*)d_in[5];
    const float* ln1_b = (const float*)d_in[6];
    const float* ln2_g = (const float*)d_in[7];
    const float* ln2_b = (const float*)d_in[8];
    const float* w1    = (const float*)d_in[9];
    const float* b1    = (const float*)d_in[10];
    const float* w2    = (const float*)d_in[11];
    const float* b2    = (const float*)d_in[12];
    float* out = (float*)d_out;

    h16 *pqh, *pql, *pk, *pvt;
    h16 *px2h, *px2l, *pctxh, *pctxl, *px3h, *px3l, *phh, *phl;
    h16 *pwa, *pwb, *pw1, *pw2;
    cudaGetSymbolAddress((void**)&pqh, g_qh);    cudaGetSymbolAddress((void**)&pql, g_ql);
    cudaGetSymbolAddress((void**)&pk, g_k);      cudaGetSymbolAddress((void**)&pvt, g_vt);
    cudaGetSymbolAddress((void**)&px2h, g_x2h);  cudaGetSymbolAddress((void**)&px2l, g_x2l);
    cudaGetSymbolAddress((void**)&pctxh, g_ctxh); cudaGetSymbolAddress((void**)&pctxl, g_ctxl);
    cudaGetSymbolAddress((void**)&px3h, g_x3h);  cudaGetSymbolAddress((void**)&px3l, g_x3l);
    cudaGetSymbolAddress((void**)&phh, g_hh);    cudaGetSymbolAddress((void**)&phl, g_hl);
    cudaGetSymbolAddress((void**)&pwa, g_wa);    cudaGetSymbolAddress((void**)&pwb, g_wb);
    cudaGetSymbolAddress((void**)&pw1, g_w1);    cudaGetSymbolAddress((void**)&pw2, g_w2);

    cudaFuncSetAttribute(gemm_mma<EPI_BIAS_RES>,   cudaFuncAttributeMaxDynamicSharedMemorySize, GEMM_SMEM);
    cudaFuncSetAttribute(gemm_mma<EPI_GELU_SPLIT>, cudaFuncAttributeMaxDynamicSharedMemorySize, GEMM_SMEM);
    cudaFuncSetAttribute(gemm_mma<EPI_QKV>,        cudaFuncAttributeMaxDynamicSharedMemorySize, GEMM_SMEM);
    cudaFuncSetAttribute(attn_mma, cudaFuncAttributeMaxDynamicSharedMemorySize, ATT_SMEM);

    // 0) weights -> single fp16 (one launch)
    split_all_kernel<<<3072, 256>>>(in_w, out_w, w1, w2, pwa, pwb, pw1, pw2);

    // 1) x2 = LN1(x)  (fp16 hi/lo)
    ln_split_kernel<<<8192, 128>>>(x, ln1_g, ln1_b, px2h, px2l);

    // 2) qkv projection -> q hi/lo (scaled), k single, v-transposed single
    {
        dim3 grid(1536 / 128, 8192 / 128);
        gemm_mma<EPI_QKV><<<grid, 128, GEMM_SMEM>>>(px2h, px2l, pwa, in_b, nullptr,
                                                    nullptr, pqh, pql, pk, pvt, 1536, 512);
    }

    // 3) ctx = sliding-window attention
    {
        dim3 grid(2048 / 64, 32);
        attn_mma<<<grid, 256, ATT_SMEM>>>(pqh, pql, pk, pvt, pctxh, pctxl);
    }

    // 4) out = x + ctx @ out_w^T + out_b
    {
        dim3 grid(512 / 128, 8192 / 128);
        gemm_mma<EPI_BIAS_RES><<<grid, 128, GEMM_SMEM>>>(pctxh, pctxl, pwb, out_b, x,
                                                         out, nullptr, nullptr, nullptr, nullptr,
                                                         512, 512);
    }

    // 5) x3 = LN2(out)
    ln_split_kernel<<<8192, 128>>>(out, ln2_g, ln2_b, px3h, px3l);

    // 6) h = gelu(x3 @ w1^T + b1)  (fp16 hi/lo)
    {
        dim3 grid(2048 / 128, 8192 / 128);
        gemm_mma<EPI_GELU_SPLIT><<<grid, 128, GEMM_SMEM>>>(px3h, px3l, pw1, b1, nullptr,
                                                           nullptr, phh, phl, nullptr, nullptr,
                                                           2048, 512);
    }

    // 7) out = out + h @ w2^T + b2
    {
        dim3 grid(512 / 128, 8192 / 128);
        gemm_mma<EPI_BIAS_RES><<<grid, 128, GEMM_SMEM>>>(phh, phl, pw2, b2, out,
                                                         out, nullptr, nullptr, nullptr, nullptr,
                                                         512, 2048);
    }
}

// round 12
// speedup vs baseline: 6.7398x; 1.7121x over previous
#include <cuda_runtime.h>
#include <cuda_fp16.h>
#include <math.h>
#include <stdint.h>

typedef __half h16;

// B=4, T=2048, D=512, H=8, HD=64, F=2048, WINDOW=128, rows=8192

// ---------------- scratch ----------------
__device__ h16  g_q  [32 * 2048 * 64];   // [bh][t][d], scaled
__device__ h16  g_k  [32 * 2048 * 64];   // [bh][t][d]
__device__ h16  g_vt [32 * 64 * 2048];   // [bh][d][t]
__device__ h16  g_x2 [8192 * 512];
__device__ h16  g_ctx[8192 * 512];
__device__ h16  g_x3 [8192 * 512];
__device__ h16  g_h  [8192 * 2048];
__device__ h16  g_wa [1536 * 512];
__device__ h16  g_wb [512 * 512];
__device__ h16  g_w1 [2048 * 512];
__device__ h16  g_w2 [512 * 2048];

// ---------------- helpers ----------------
__device__ __forceinline__ uint32_t smem_u32(const void* p) {
    uint32_t a;
    asm("{ .reg .u64 t; cvta.to.shared.u64 t, %1; cvt.u32.u64 %0, t; }" : "=r"(a) : "l"(p));
    return a;
}
__device__ __forceinline__ void cp16(uint32_t d, const void* g) {
    asm volatile("cp.async.cg.shared.global [%0], [%1], 16;" :: "r"(d), "l"(g));
}
__device__ __forceinline__ void cp16z(uint32_t d, const void* g, uint32_t srcsz) {
    asm volatile("cp.async.cg.shared.global [%0], [%1], 16, %2;" :: "r"(d), "l"(g), "r"(srcsz));
}
#define CP_COMMIT() asm volatile("cp.async.commit_group;" ::: "memory")
#define CP_WAIT(n)  asm volatile("cp.async.wait_group %0;" :: "n"(n) : "memory")

#define LDSM4(r, addr) \
    asm volatile("ldmatrix.sync.aligned.m8n8.x4.shared.b16 {%0,%1,%2,%3}, [%4];" \
        : "=r"((r)[0]), "=r"((r)[1]), "=r"((r)[2]), "=r"((r)[3]) : "r"(addr))

#define MMA16816(c, a, b) \
    asm volatile("mma.sync.aligned.m16n8k16.row.col.f32.f16.f16.f32 " \
        "{%0,%1,%2,%3}, {%4,%5,%6,%7}, {%8,%9}, {%0,%1,%2,%3};" \
        : "+f"((c)[0]), "+f"((c)[1]), "+f"((c)[2]), "+f"((c)[3]) \
        : "r"((a)[0]), "r"((a)[1]), "r"((a)[2]), "r"((a)[3]), "r"((b)[0]), "r"((b)[1]))

__device__ __forceinline__ void cvtH2(float a, float b, h16* p) {
    *(__half2*)p = __halves2half2(__float2half_rn(a), __float2half_rn(b));
}

// ---------------- fused weight convert ----------------
__global__ void split_all_kernel(const float* __restrict__ in_w, const float* __restrict__ out_w,
                                 const float* __restrict__ w1, const float* __restrict__ w2,
                                 h16* __restrict__ wa, h16* __restrict__ wb,
                                 h16* __restrict__ w1o, h16* __restrict__ w2o) {
    int i = blockIdx.x * 256 + threadIdx.x;   // unit = 4 floats; total 786432
    const float* src; h16* dst; int off;
    if (i < 196608)      { src = in_w;  dst = wa;  off = i; }
    else if (i < 262144) { src = out_w; dst = wb;  off = i - 196608; }
    else if (i < 524288) { src = w1;    dst = w1o; off = i - 262144; }
    else                 { src = w2;    dst = w2o; off = i - 524288; }
    float4 v = *(const float4*)(src + (size_t)off * 4);
    cvtH2(v.x, v.y, dst + (size_t)off * 4);
    cvtH2(v.z, v.w, dst + (size_t)off * 4 + 2);
}

// ---------------- LayerNorm -> single fp16 ----------------
__global__ void ln_h_kernel(const float* __restrict__ x, const float* __restrict__ gw,
                            const float* __restrict__ bw, h16* __restrict__ o) {
    int row = blockIdx.x;
    int t = threadIdx.x;
    const float* xr = x + (size_t)row * 512;
    float4 v = *(const float4*)(xr + t * 4);
    float s  = v.x + v.y + v.z + v.w;
    float sq = v.x * v.x + v.y * v.y + v.z * v.z + v.w * v.w;
    #pragma unroll
    for (int of = 16; of > 0; of >>= 1) {
        s  += __shfl_xor_sync(0xffffffffu, s,  of);
        sq += __shfl_xor_sync(0xffffffffu, sq, of);
    }
    __shared__ float red[8];
    int wid = t >> 5, lane = t & 31;
    if (lane == 0) { red[wid] = s; red[4 + wid] = sq; }
    __syncthreads();
    float S  = red[0] + red[1] + red[2] + red[3];
    float SQ = red[4] + red[5] + red[6] + red[7];
    float mu   = S * (1.0f / 512.0f);
    float var  = SQ * (1.0f / 512.0f) - mu * mu;
    float rstd = rsqrtf(var + 1e-5f);
    float4 gv = *(const float4*)(gw + t * 4);
    float4 bv = *(const float4*)(bw + t * 4);
    float o0 = (v.x - mu) * rstd * gv.x + bv.x;
    float o1 = (v.y - mu) * rstd * gv.y + bv.y;
    float o2 = (v.z - mu) * rstd * gv.z + bv.z;
    float o3 = (v.w - mu) * rstd * gv.w + bv.w;
    size_t base = (size_t)row * 512 + t * 4;
    cvtH2(o0, o1, o + base);
    cvtH2(o2, o3, o + base + 2);
}

// ---------------- mma.sync GEMM: C = A @ W^T, single fp16 operands ----------------
// CTA 128x128, 4 warps of 64x64, BK=32, 4-stage cp.async (64KB -> 3 CTAs/SM).
#define EPI_BIAS_RES   1
#define EPI_GELU       2
#define EPI_QKV        3

#define TILE_B   8192            // 128 rows x 64 B
#define STAGE_B  (2 * TILE_B)    // 16384 (A, W)
#define NSTAGE   4
#define GEMM_SMEM (NSTAGE * STAGE_B)   // 65536

#define SWIZ(row, chunk) ((row) * 64 + (((chunk) ^ (((row) >> 1) & 3)) << 4))

template<int EPI>
__global__ __launch_bounds__(128)
void gemm_mma(const h16* __restrict__ A, const h16* __restrict__ W,
              const float* __restrict__ bias, const float* __restrict__ res,
              float* __restrict__ Cf, h16* __restrict__ Ch,
              h16* __restrict__ Kh, h16* __restrict__ Vth,
              int N, int K) {
    extern __shared__ char sm[];
    const int tid = threadIdx.x;
    const int lane = tid & 31, wid = tid >> 5;
    const int wm = wid & 1, wn = wid >> 1;
    const int m0 = blockIdx.y * 128, n0 = blockIdx.x * 128;
    const uint32_t sbase = smem_u32(sm);

    const h16* srcs[2] = { A + (size_t)m0 * K, W + (size_t)n0 * K };

    auto load_stage = [&](int s, int kb) {
        uint32_t so = sbase + (uint32_t)s * STAGE_B;
        #pragma unroll
        for (int tt = 0; tt < 2; tt++) {
            const h16* gp = srcs[tt] + kb * 32;
            uint32_t tb = so + tt * TILE_B;
            #pragma unroll
            for (int it = 0; it < 4; it++) {
                int idx = tid + it * 128;          // 0..511
                int r = idx >> 2, c = idx & 3;
                cp16(tb + SWIZ(r, c), gp + (size_t)r * K + c * 8);
            }
        }
    };

    float acc[4][8][4];
    #pragma unroll
    for (int i = 0; i < 4; i++)
        #pragma unroll
        for (int j = 0; j < 8; j++)
            #pragma unroll
            for (int r = 0; r < 4; r++) acc[i][j][r] = 0.0f;

    const int nkb = K >> 5;

    load_stage(0, 0); CP_COMMIT();
    load_stage(1, 1); CP_COMMIT();
    load_stage(2, 2); CP_COMMIT();

    const uint32_t aRow = wm * 64 + (lane & 15);
    const uint32_t aChunkHalf = (lane >> 4);
    const uint32_t bRow = wn * 64 + (lane & 7) + ((lane >> 4) << 3);
    const uint32_t bChunkHalf = (lane >> 3) & 1;

    for (int kb = 0; kb < nkb; kb++) {
        bool more = (kb + NSTAGE - 1) < nkb;
        if (more) { CP_WAIT(NSTAGE - 2); } else { CP_WAIT(0); }
        __syncthreads();
        if (more) { load_stage((kb + NSTAGE - 1) % NSTAGE, kb + NSTAGE - 1); CP_COMMIT(); }

        uint32_t so = sbase + (uint32_t)(kb % NSTAGE) * STAGE_B;
        #pragma unroll
        for (int ks = 0; ks < 2; ks++) {
            const uint32_t kcA = ks * 2 + aChunkHalf;
            const uint32_t kcB = ks * 2 + bChunkHalf;
            uint32_t Af[4][4];
            #pragma unroll
            for (int i = 0; i < 4; i++)
                LDSM4(Af[i], so + SWIZ(aRow + i * 16, kcA));
            uint32_t Wf[4][4];
            #pragma unroll
            for (int jp = 0; jp < 4; jp++)
                LDSM4(Wf[jp], so + TILE_B + SWIZ(bRow + jp * 16, kcB));
            #pragma unroll
            for (int i = 0; i < 4; i++) {
                #pragma unroll
                for (int j = 0; j < 8; j++) {
                    int jp = j >> 1, jo = (j & 1) * 2;
                    MMA16816(acc[i][j], Af[i], (Wf[jp] + jo));
                }
            }
        }
    }

    // ---------------- epilogue ----------------
    #pragma unroll
    for (int i = 0; i < 4; i++) {
        int rb = m0 + wm * 64 + i * 16 + (lane >> 2);
        #pragma unroll
        for (int j = 0; j < 8; j++) {
            int col = n0 + wn * 64 + j * 8 + (lane & 3) * 2;
            float b0 = bias[col], b1 = bias[col + 1];
            #pragma unroll
            for (int half = 0; half < 2; half++) {
                int row = rb + half * 8;
                float o0 = acc[i][j][half * 2 + 0] + b0;
                float o1 = acc[i][j][half * 2 + 1] + b1;
                if (EPI == EPI_QKV) {
                    int b = row >> 11, t = row & 2047;
                    if (col < 512) {
                        int h = col >> 6, d = col & 63;
                        size_t ob = ((size_t)(b * 8 + h) * 2048 + t) * 64 + d;
                        cvtH2(o0 * 0.125f, o1 * 0.125f, Ch + ob);
                    } else if (col < 1024) {
                        int c = col - 512;
                        int h = c >> 6, d = c & 63;
                        size_t ob = ((size_t)(b * 8 + h) * 2048 + t) * 64 + d;
                        cvtH2(o0, o1, Kh + ob);
                    } else {
                        int c = col - 1024;
                        int h = c >> 6, d = c & 63;
                        size_t ob = ((size_t)(b * 8 + h) * 64 + d) * 2048 + t;
                        Vth[ob]        = __float2half_rn(o0);
                        Vth[ob + 2048] = __float2half_rn(o1);
                    }
                    continue;
                }
                size_t ob = (size_t)row * N + col;
                if (EPI == EPI_BIAS_RES) {
                    float2 rv = *(const float2*)(res + ob);
                    o0 += rv.x; o1 += rv.y;
                    float2 o = make_float2(o0, o1);
                    *(float2*)(Cf + ob) = o;
                }
                if (EPI == EPI_GELU) {
                    o0 = 0.5f * o0 * (1.0f + erff(o0 * 0.70710678118654752f));
                    o1 = 0.5f * o1 * (1.0f + erff(o1 * 0.70710678118654752f));
                    cvtH2(o0, o1, Ch + ob);
                }
            }
        }
    }
}

// ---------------- mma attention (all single fp16) ----------------
// block = (qtile 64, bh). keys = 192. 256 threads / 8 warps. smem 88.3KB -> 2 CTAs/SM.
#define AQ     0u          // Q: 64 x 144
#define AK     9216u       // K: 192 x 144
#define AV     36864u      // VT: 64 x 400
#define AP     62464u      // P fp16: 64 x 400
#define AS     0u          // S fp16 overlay (64 x 400 = 25600 over Q+K region)
#define ASUM   88064u
#define ATT_SMEM 88320u

__global__ __launch_bounds__(256)
void attn_mma(const h16* __restrict__ qq, const h16* __restrict__ kk,
              const h16* __restrict__ vt, h16* __restrict__ ctx) {
    extern __shared__ char sm[];
    const uint32_t sb = smem_u32(sm);
    const int tid = threadIdx.x;
    const int lane = tid & 31, wid = tid >> 5;
    const int bh = blockIdx.y;
    const int t0 = blockIdx.x * 64;
    const int kbase = t0 - 128;

    // ---- loads ----
    {
        #pragma unroll
        for (int it = 0; it < 2; it++) {
            int idx = tid + it * 256;
            int r = idx >> 3, c = idx & 7;
            cp16(sb + AQ + r * 144 + c * 16, qq + ((size_t)bh * 2048 + t0 + r) * 64 + c * 8);
        }
        #pragma unroll
        for (int it = 0; it < 6; it++) {
            int idx = tid + it * 256;
            int r = idx >> 3, c = idx & 7;
            int s = kbase + r;
            uint32_t sz = (s >= 0) ? 16u : 0u;
            int sc = s < 0 ? 0 : s;
            cp16z(sb + AK + r * 144 + c * 16, kk + ((size_t)bh * 2048 + sc) * 64 + c * 8, sz);
        }
        #pragma unroll
        for (int it = 0; it < 6; it++) {
            int idx = tid + it * 256;
            int r = idx / 24, c = idx - r * 24;
            int scol = kbase + c * 8;
            uint32_t sz = (scol >= 0) ? 16u : 0u;
            int sc = scol < 0 ? 0 : scol;
            cp16z(sb + AV + r * 400 + c * 16, vt + ((size_t)bh * 64 + r) * 2048 + sc, sz);
        }
    }
    CP_COMMIT();
    CP_WAIT(0);
    __syncthreads();

    // ---- phase 1: S = Q @ K^T (single term) ----
    const int mt = wid & 3;
    const int nh = wid >> 2;
    float Sacc[12][4];
    #pragma unroll
    for (int j = 0; j < 12; j++)
        #pragma unroll
        for (int r = 0; r < 4; r++) Sacc[j][r] = 0.0f;

    const uint32_t aOffBase = (mt * 16 + (lane & 15)) * 144;
    const uint32_t aHalf = (lane >> 4);
    const uint32_t bRowOff = (lane & 7) + ((lane >> 4) << 3);
    const uint32_t bHalf = (lane >> 3) & 1;

    #pragma unroll
    for (int kc = 0; kc < 4; kc++) {
        uint32_t ah[4];
        LDSM4(ah, sb + AQ + aOffBase + (kc * 2 + aHalf) * 16);
        #pragma unroll
        for (int jp = 0; jp < 6; jp++) {
            uint32_t bf[4];
            uint32_t boff = (nh * 96 + jp * 16 + bRowOff) * 144 + (kc * 2 + bHalf) * 16;
            LDSM4(bf, sb + AK + boff);
            #pragma unroll
            for (int jj = 0; jj < 2; jj++) {
                int j = jp * 2 + jj, jo = jj * 2;
                MMA16816(Sacc[j], ah, (bf + jo));
            }
        }
    }
    __syncthreads();   // Q and K reads done -> S may overlay them

    // write S (fp16)
    {
        int r0 = mt * 16 + (lane >> 2);
        #pragma unroll
        for (int j = 0; j < 12; j++) {
            int cc = nh * 96 + j * 8 + (lane & 3) * 2;
            cvtH2(Sacc[j][0], Sacc[j][1], (h16*)(sm + AS + r0 * 400 + cc * 2));
            cvtH2(Sacc[j][2], Sacc[j][3], (h16*)(sm + AS + (r0 + 8) * 400 + cc * 2));
        }
    }
    __syncthreads();

    // ---- phase 2: softmax ----
    {
        int r = tid >> 2, tg = tid & 3;
        const h16* Sp = (const h16*)(sm + AS + r * 400);
        int jlo = r + 1;
        if (kbase < 0 && jlo < -kbase) jlo = -kbase;
        int jhi = r + 128;
        float mx = -1e30f;
        #pragma unroll 8
        for (int j2 = 0; j2 < 48; j2++) {
            int j = tg * 48 + j2;
            float v = __half2float(Sp[j]);
            bool ok = (j >= jlo) && (j <= jhi);
            mx = fmaxf(mx, ok ? v : -1e30f);
        }
        mx = fmaxf(mx, __shfl_xor_sync(0xffffffffu, mx, 1));
        mx = fmaxf(mx, __shfl_xor_sync(0xffffffffu, mx, 2));
        float sum = 0.0f;
        #pragma unroll 4
        for (int j2 = 0; j2 < 48; j2 += 2) {
            int j = tg * 48 + j2;
            float v0 = __half2float(Sp[j]), v1 = __half2float(Sp[j + 1]);
            bool ok0 = (j >= jlo) && (j <= jhi);
            bool ok1 = (j + 1 >= jlo) && (j + 1 <= jhi);
            float p0 = ok0 ? __expf(v0 - mx) : 0.0f;
            float p1 = ok1 ? __expf(v1 - mx) : 0.0f;
            sum += p0 + p1;
            cvtH2(p0, p1, (h16*)(sm + AP + r * 400 + j * 2));
        }
        sum += __shfl_xor_sync(0xffffffffu, sum, 1);
        sum += __shfl_xor_sync(0xffffffffu, sum, 2);
        if (tg == 0) *(float*)(sm + ASUM + r * 4) = sum;
    }
    __syncthreads();

    // ---- phase 3: ctx = P @ V (single term) ----
    const int dh = wid >> 2;
    float Cacc[4][4];
    #pragma unroll
    for (int j = 0; j < 4; j++)
        #pragma unroll
        for (int r = 0; r < 4; r++) Cacc[j][r] = 0.0f;

    const uint32_t pOffBase = (mt * 16 + (lane & 15)) * 400;
    #pragma unroll
    for (int kc = 0; kc < 12; kc++) {
        uint32_t pa[4];
        LDSM4(pa, sb + AP + pOffBase + (kc * 2 + aHalf) * 16);
        #pragma unroll
        for (int jp = 0; jp < 2; jp++) {
            uint32_t vb[4];
            uint32_t voff = (dh * 32 + jp * 16 + bRowOff) * 400 + (kc * 2 + bHalf) * 16;
            LDSM4(vb, sb + AV + voff);
            #pragma unroll
            for (int jj = 0; jj < 2; jj++) {
                int j = jp * 2 + jj, jo = jj * 2;
                MMA16816(Cacc[j], pa, (vb + jo));
            }
        }
    }

    // epilogue: divide by row sums, store ctx single fp16
    {
        int b = bh >> 3, h = bh & 7;
        int rl0 = mt * 16 + (lane >> 2);
        float inv0 = 1.0f / *(const float*)(sm + ASUM + rl0 * 4);
        float inv1 = 1.0f / *(const float*)(sm + ASUM + (rl0 + 8) * 4);
        #pragma unroll
        for (int j = 0; j < 4; j++) {
            int d = dh * 32 + j * 8 + (lane & 3) * 2;
            size_t ob0 = ((size_t)(b * 2048 + t0 + rl0)) * 512 + h * 64 + d;
            size_t ob1 = ob0 + (size_t)8 * 512;
            cvtH2(Cacc[j][0] * inv0, Cacc[j][1] * inv0, ctx + ob0);
            cvtH2(Cacc[j][2] * inv1, Cacc[j][3] * inv1, ctx + ob1);
        }
    }
}

// ---------------- launch ----------------
extern "C" void kernel_launch(void* const* d_in, const int* in_sizes, int n_in,
                              void* d_out, int out_size) {
    const float* x     = (const float*)d_in[0];
    const float* in_w  = (const float*)d_in[1];
    const float* in_b  = (const float*)d_in[2];
    const float* out_w = (const float*)d_in[3];
    const float* out_b = (const float*)d_in[4];
    const float* ln1_g = (const float*)d_in[5];
    const float* ln1_b = (const float*)d_in[6];
    const float* ln2_g = (const float*)d_in[7];
    const float* ln2_b = (const float*)d_in[8];
    const float* w1    = (const float*)d_in[9];
    const float* b1    = (const float*)d_in[10];
    const float* w2    = (const float*)d_in[11];
    const float* b2    = (const float*)d_in[12];
    float* out = (float*)d_out;

    h16 *pq, *pk, *pvt, *px2, *pctx, *px3, *ph;
    h16 *pwa, *pwb, *pw1, *pw2;
    cudaGetSymbolAddress((void**)&pq, g_q);      cudaGetSymbolAddress((void**)&pk, g_k);
    cudaGetSymbolAddress((void**)&pvt, g_vt);
    cudaGetSymbolAddress((void**)&px2, g_x2);    cudaGetSymbolAddress((void**)&pctx, g_ctx);
    cudaGetSymbolAddress((void**)&px3, g_x3);    cudaGetSymbolAddress((void**)&ph, g_h);
    cudaGetSymbolAddress((void**)&pwa, g_wa);    cudaGetSymbolAddress((void**)&pwb, g_wb);
    cudaGetSymbolAddress((void**)&pw1, g_w1);    cudaGetSymbolAddress((void**)&pw2, g_w2);

    cudaFuncSetAttribute(gemm_mma<EPI_BIAS_RES>, cudaFuncAttributeMaxDynamicSharedMemorySize, GEMM_SMEM);
    cudaFuncSetAttribute(gemm_mma<EPI_GELU>,     cudaFuncAttributeMaxDynamicSharedMemorySize, GEMM_SMEM);
    cudaFuncSetAttribute(gemm_mma<EPI_QKV>,      cudaFuncAttributeMaxDynamicSharedMemorySize, GEMM_SMEM);
    cudaFuncSetAttribute(attn_mma, cudaFuncAttributeMaxDynamicSharedMemorySize, ATT_SMEM);

    // 0) weights -> fp16
    split_all_kernel<<<3072, 256>>>(in_w, out_w, w1, w2, pwa, pwb, pw1, pw2);

    // 1) x2 = LN1(x)
    ln_h_kernel<<<8192, 128>>>(x, ln1_g, ln1_b, px2);

    // 2) qkv projection -> q (scaled), k, v-transposed
    {
        dim3 grid(1536 / 128, 8192 / 128);
        gemm_mma<EPI_QKV><<<grid, 128, GEMM_SMEM>>>(px2, pwa, in_b, nullptr,
                                                    nullptr, pq, pk, pvt, 1536, 512);
    }

    // 3) ctx = sliding-window attention
    {
        dim3 grid(2048 / 64, 32);
        attn_mma<<<grid, 256, ATT_SMEM>>>(pq, pk, pvt, pctx);
    }

    // 4) out = x + ctx @ out_w^T + out_b
    {
        dim3 grid(512 / 128, 8192 / 128);
        gemm_mma<EPI_BIAS_RES><<<grid, 128, GEMM_SMEM>>>(pctx, pwb, out_b, x,
                                                         out, nullptr, nullptr, nullptr,
                                                         512, 512);
    }

    // 5) x3 = LN2(out)
    ln_h_kernel<<<8192, 128>>>(out, ln2_g, ln2_b, px3);

    // 6) h = gelu(x3 @ w1^T + b1)
    {
        dim3 grid(2048 / 128, 8192 / 128);
        gemm_mma<EPI_GELU><<<grid, 128, GEMM_SMEM>>>(px3, pw1, b1, nullptr,
                                                     nullptr, ph, nullptr, nullptr,
                                                     2048, 512);
    }

    // 7) out = out + h @ w2^T + b2
    {
        dim3 grid(512 / 128, 8192 / 128);
        gemm_mma<EPI_BIAS_RES><<<grid, 128, GEMM_SMEM>>>(ph, pw2, b2, out,
                                                         out, nullptr, nullptr, nullptr,
                                                         512, 2048);
    }
}